// round 1
// baseline (speedup 1.0000x reference)
#include <cuda_runtime.h>

#define B_  4
#define L_  4096
#define H_  16
#define D_  64
#define C_  1024
#define KNL 13

// Scratch (device globals: no allocation allowed)
__device__ float g_q[(size_t)B_*H_*L_*D_];
__device__ float g_k[(size_t)B_*H_*L_*D_];
__device__ float g_v[(size_t)B_*H_*L_*D_];
__device__ float g_att[(size_t)B_*L_*C_];

typedef unsigned long long u64;

__device__ __forceinline__ u64 bc2(float x) {
    u64 r; unsigned xi = __float_as_uint(x);
    asm("mov.b64 %0, {%1, %1};" : "=l"(r) : "r"(xi));
    return r;
}
__device__ __forceinline__ void fma2(u64& d, u64 a, u64 b) {
    asm("fma.rn.f32x2 %0, %1, %2, %0;" : "+l"(d) : "l"(a), "l"(b));
}

__device__ __forceinline__ void write_qkv(int r, int c, float v) {
    int which = c >> 10;
    int rem = c & 1023;
    int h = rem >> 6, d = rem & 63;
    int b = r >> 12, l = r & 4095;
    size_t idx = ((((size_t)b * H_ + h) * L_) + l) * D_ + d;
    if (which == 0)      g_q[idx] = v * 0.125f;   // SCALE = 64^-0.5
    else if (which == 1) g_k[idx] = v;
    else                 g_v[idx] = v;
}

// 128x128x8 tiled SGEMM, 256 threads, 8x8 microtile, f32x2 packed FMA.
// mode 0: C = A@B + bias, scattered into g_q/g_k/g_v (QKV).
// mode 1: C = g_att@B + bias -> Cout (A passed as nullptr).
__global__ __launch_bounds__(256) void gemm_kernel(
    const float* __restrict__ A, const float* __restrict__ Bm,
    const float* __restrict__ bias, float* __restrict__ Cout,
    int M, int N, int K, int mode)
{
    __shared__ float As[8][132];
    __shared__ float Bs[8][132];

    const float* Ap = (A == nullptr) ? g_att : A;

    int tid = threadIdx.x;
    int tx = tid & 15, ty = tid >> 4;
    int m0 = blockIdx.y * 128, n0 = blockIdx.x * 128;

    u64 acc[8][4];
    #pragma unroll
    for (int i = 0; i < 8; i++)
        #pragma unroll
        for (int j = 0; j < 4; j++) acc[i][j] = 0ull;

    int arow = tid >> 1, akq = (tid & 1) * 4;   // A tile: 128 rows x 8 k
    int br   = tid >> 5, bc  = (tid & 31) * 4;  // B tile: 8 rows x 128 cols

    const float* Aptr = Ap + (size_t)(m0 + arow) * K + akq;
    const float* Bptr = Bm + (size_t)br * N + n0 + bc;

    for (int kt = 0; kt < K; kt += 8) {
        float4 av = *(const float4*)(Aptr + kt);
        As[akq + 0][arow] = av.x;
        As[akq + 1][arow] = av.y;
        As[akq + 2][arow] = av.z;
        As[akq + 3][arow] = av.w;
        float4 bv = *(const float4*)(Bptr + (size_t)kt * N);
        *(float4*)&Bs[br][bc] = bv;
        __syncthreads();

        #pragma unroll
        for (int k = 0; k < 8; k++) {
            float a[8];
            *(float4*)(a)     = *(const float4*)&As[k][ty * 8];
            *(float4*)(a + 4) = *(const float4*)&As[k][ty * 8 + 4];
            u64 b2[4];
            const u64* bp = (const u64*)&Bs[k][tx * 8];
            b2[0] = bp[0]; b2[1] = bp[1]; b2[2] = bp[2]; b2[3] = bp[3];
            #pragma unroll
            for (int i = 0; i < 8; i++) {
                u64 a2 = bc2(a[i]);
                #pragma unroll
                for (int j = 0; j < 4; j++) fma2(acc[i][j], a2, b2[j]);
            }
        }
        __syncthreads();
    }

    int rbase = m0 + ty * 8;
    int cbase = n0 + tx * 8;
    #pragma unroll
    for (int i = 0; i < 8; i++) {
        int r = rbase + i;
        #pragma unroll
        for (int j = 0; j < 4; j++) {
            float lo = __uint_as_float((unsigned)(acc[i][j] & 0xffffffffull));
            float hi = __uint_as_float((unsigned)(acc[i][j] >> 32));
            int c0 = cbase + 2 * j;
            float v0 = lo + bias[c0];
            float v1 = hi + bias[c0 + 1];
            if (mode == 0) {
                write_qkv(r, c0, v0);
                write_qkv(r, c0 + 1, v1);
            } else {
                Cout[(size_t)r * N + c0]     = v0;
                Cout[(size_t)r * N + c0 + 1] = v1;
            }
        }
    }
}

// Neighborhood attention: block = (128-position tile, b*h). Transposed smem
// tiles: kv[d][col] stride 145 (145 % 32 = 17, coprime -> conflict-free),
// q/out[d][l] stride 129 (= 1 mod 32, conflict-free).
#define LT  128
#define KVW 145
#define QW  129
#define NA_SMEM ((64 * KVW + 64 * QW) * 4)

extern __shared__ float na_sm[];

__global__ __launch_bounds__(128) void na_kernel(const float* __restrict__ rpb)
{
    float* kv = na_sm;               // 64 x 145
    float* qo = na_sm + 64 * KVW;    // 64 x 129

    int tid = threadIdx.x;
    int n0 = blockIdx.x * LT;
    int bh = blockIdx.y;
    int h = bh & (H_ - 1);

    const float* kbase = g_k + (size_t)bh * L_ * D_;
    const float* vbase = g_v + (size_t)bh * L_ * D_;
    const float* qbase = g_q + (size_t)bh * L_ * D_;

    // load K tile transposed (halo of 6 each side -> 140 cols)
    for (int idx = tid; idx < 140 * 64; idx += 128) {
        int col = idx >> 6, d = idx & 63;
        int p = n0 - 6 + col;
        p = max(0, min(p, L_ - 1));
        kv[d * KVW + col] = kbase[(size_t)p * 64 + d];
    }
    // load Q tile transposed
    for (int idx = tid; idx < LT * 64; idx += 128) {
        int l = idx >> 6, d = idx & 63;
        qo[d * QW + l] = qbase[(size_t)(n0 + l) * 64 + d];
    }
    __syncthreads();

    int l = tid;
    int lg = n0 + l;
    int ni = max(0, min(lg - (KNL / 2), L_ - KNL));
    int col0 = ni - (n0 - 6);

    float s[KNL];
    #pragma unroll
    for (int j = 0; j < KNL; j++) s[j] = 0.f;

    for (int d = 0; d < 64; d++) {
        float qd = qo[d * QW + l];
        const float* krow = &kv[d * KVW + col0];
        #pragma unroll
        for (int j = 0; j < KNL; j++) s[j] += qd * krow[j];
    }

    int pb = h * (2 * KNL - 1) + (ni - lg + (KNL - 1));
    float mx = -1e30f;
    #pragma unroll
    for (int j = 0; j < KNL; j++) { s[j] += rpb[pb + j]; mx = fmaxf(mx, s[j]); }
    float sum = 0.f;
    #pragma unroll
    for (int j = 0; j < KNL; j++) { s[j] = __expf(s[j] - mx); sum += s[j]; }
    float inv = 1.f / sum;
    #pragma unroll
    for (int j = 0; j < KNL; j++) s[j] *= inv;

    __syncthreads();
    // load V tile transposed (reuse kv buffer)
    for (int idx = tid; idx < 140 * 64; idx += 128) {
        int col = idx >> 6, d = idx & 63;
        int p = n0 - 6 + col;
        p = max(0, min(p, L_ - 1));
        kv[d * KVW + col] = vbase[(size_t)p * 64 + d];
    }
    __syncthreads();

    for (int d = 0; d < 64; d++) {
        const float* vrow = &kv[d * KVW + col0];
        float o = 0.f;
        #pragma unroll
        for (int j = 0; j < KNL; j++) o += s[j] * vrow[j];
        qo[d * QW + l] = o;   // q no longer needed
    }
    __syncthreads();

    // store out: layout [B, L, H*D]
    int b = bh >> 4;
    float* obase = g_att + ((size_t)b * L_ + n0) * C_ + h * 64;
    for (int idx = tid; idx < LT * 64; idx += 128) {
        int l2 = idx >> 6, d = idx & 63;
        obase[(size_t)l2 * C_ + d] = qo[d * QW + l2];
    }
}

extern "C" void kernel_launch(void* const* d_in, const int* in_sizes, int n_in,
                              void* d_out, int out_size)
{
    const float* x      = (const float*)d_in[0];
    const float* w_qkv  = (const float*)d_in[1];
    const float* b_qkv  = (const float*)d_in[2];
    const float* rpb    = (const float*)d_in[3];
    const float* w_proj = (const float*)d_in[4];
    const float* b_proj = (const float*)d_in[5];
    float* out = (float*)d_out;

    cudaFuncSetAttribute(na_kernel, cudaFuncAttributeMaxDynamicSharedMemorySize, NA_SMEM);

    const int M = B_ * L_;   // 16384

    // GEMM1: qkv = x @ w_qkv + b_qkv, scattered to g_q/g_k/g_v [B,H,L,D]
    gemm_kernel<<<dim3((3 * C_) / 128, M / 128), 256>>>(
        x, w_qkv, b_qkv, out, M, 3 * C_, C_, 0);

    // Neighborhood attention -> g_att [B, L, C]
    na_kernel<<<dim3(L_ / LT, B_ * H_), 128, NA_SMEM>>>(rpb);

    // GEMM2: out = g_att @ w_proj + b_proj
    gemm_kernel<<<dim3(C_ / 128, M / 128), 256>>>(
        nullptr, w_proj, b_proj, out, M, C_, C_, 1);
}

// round 3
// speedup vs baseline: 1.8849x; 1.8849x over previous
#include <cuda_runtime.h>
#include <cuda_bf16.h>
#include <cstdint>

#define B_  4
#define L_  4096
#define H_  16
#define D_  64
#define C_  1024
#define KNL 13
#define M_TOT (B_ * L_)          // 16384
#define K_TOT C_                 // 1024

// ---------------- device scratch (no allocation allowed) ----------------
__device__ float g_q[(size_t)B_*H_*L_*D_];
__device__ float g_k[(size_t)B_*H_*L_*D_];
__device__ float g_v[(size_t)B_*H_*L_*D_];
__device__ __nv_bfloat16 g_x_hi[(size_t)M_TOT*K_TOT];
__device__ __nv_bfloat16 g_x_lo[(size_t)M_TOT*K_TOT];
__device__ __nv_bfloat16 g_att_hi[(size_t)M_TOT*K_TOT];
__device__ __nv_bfloat16 g_att_lo[(size_t)M_TOT*K_TOT];
__device__ __nv_bfloat16 g_wqkvT_hi[(size_t)3*C_*C_];
__device__ __nv_bfloat16 g_wqkvT_lo[(size_t)3*C_*C_];
__device__ __nv_bfloat16 g_wprojT_hi[(size_t)C_*C_];
__device__ __nv_bfloat16 g_wprojT_lo[(size_t)C_*C_];

// ---------------- helpers ----------------
__device__ __forceinline__ uint32_t smem_u32(const void* p) {
    uint32_t a;
    asm("{ .reg .u64 t; cvta.to.shared.u64 t, %1; cvt.u32.u64 %0, t; }"
        : "=r"(a) : "l"(p));
    return a;
}
__device__ __forceinline__ void cpa16(uint32_t dst, const void* src) {
    asm volatile("cp.async.cg.shared.global [%0], [%1], 16;" :: "r"(dst), "l"(src));
}
#define CP_COMMIT() asm volatile("cp.async.commit_group;" ::: "memory")
#define CP_WAIT1()  asm volatile("cp.async.wait_group 1;" ::: "memory")

#define LDSM_X4(r, addr) \
    asm volatile("ldmatrix.sync.aligned.m8n8.x4.shared.b16 {%0,%1,%2,%3}, [%4];" \
        : "=r"((r)[0]), "=r"((r)[1]), "=r"((r)[2]), "=r"((r)[3]) : "r"(addr))

#define MMA_BF16(acc, a, b0v, b1v) \
    asm volatile("mma.sync.aligned.m16n8k16.row.col.f32.bf16.bf16.f32 " \
        "{%0,%1,%2,%3},{%4,%5,%6,%7},{%8,%9},{%0,%1,%2,%3};" \
        : "+f"((acc)[0]), "+f"((acc)[1]), "+f"((acc)[2]), "+f"((acc)[3]) \
        : "r"((a)[0]), "r"((a)[1]), "r"((a)[2]), "r"((a)[3]), "r"(b0v), "r"(b1v))

// ---------------- conversion kernels ----------------
__global__ __launch_bounds__(256) void convert_split_kernel(
    const float* __restrict__ src, __nv_bfloat16* __restrict__ hi,
    __nv_bfloat16* __restrict__ lo, size_t n4)
{
    size_t i = (size_t)blockIdx.x * 256 + threadIdx.x;
    if (i >= n4) return;
    float4 v = ((const float4*)src)[i];
    float vv[4] = {v.x, v.y, v.z, v.w};
    unsigned long long ph = 0, pl = 0;
    #pragma unroll
    for (int j = 0; j < 4; j++) {
        __nv_bfloat16 h = __float2bfloat16(vv[j]);
        __nv_bfloat16 l = __float2bfloat16(vv[j] - __bfloat162float(h));
        ph |= (unsigned long long)(*(unsigned short*)&h) << (16 * j);
        pl |= (unsigned long long)(*(unsigned short*)&l) << (16 * j);
    }
    ((unsigned long long*)hi)[i] = ph;
    ((unsigned long long*)lo)[i] = pl;
}

// transpose + split: w [K][N] fp32 -> wT_hi/lo [N][K] bf16
__global__ __launch_bounds__(1024) void transpose_split_kernel(
    const float* __restrict__ w, __nv_bfloat16* __restrict__ thi,
    __nv_bfloat16* __restrict__ tlo, int K, int N)
{
    __shared__ float sm[32][33];
    int n0 = blockIdx.x * 32, k0 = blockIdx.y * 32;
    int tx = threadIdx.x, ty = threadIdx.y;
    sm[ty][tx] = w[(size_t)(k0 + ty) * N + n0 + tx];
    __syncthreads();
    float v = sm[tx][ty];
    __nv_bfloat16 h = __float2bfloat16(v);
    __nv_bfloat16 l = __float2bfloat16(v - __bfloat162float(h));
    size_t o = (size_t)(n0 + ty) * K + k0 + tx;
    thi[o] = h;
    tlo[o] = l;
}

// ---------------- HMMA split-bf16 GEMM ----------------
// CTA 128x128, 8 warps (2M x 4N grid, warp tile 64x32), K chunk 64, 2 stages.
// Stage layout: Ah @0 (16K) | Al @16K | Bh @32K | Bl @48K ; stage stride 64K.
#define STG 65536
#define GEMM_SMEM (2 * STG + 1024)
#define NCHUNK (K_TOT / 64)

extern __shared__ char gsm_raw[];

__device__ __forceinline__ void ld_stage(
    uint32_t sb, const __nv_bfloat16* Ah, const __nv_bfloat16* Al,
    const __nv_bfloat16* Bh, const __nv_bfloat16* Bl,
    int m0, int n0, int kc, int tid)
{
    #pragma unroll
    for (int i = 0; i < 4; i++) {
        int e = tid + i * 256;               // 0..1023
        int row = e >> 3, c16 = e & 7;
        uint32_t off = row * 128 + c16 * 16;
        uint32_t sw = off ^ (uint32_t)((row & 7) << 4);
        size_t ga = (size_t)(m0 + row) * K_TOT + kc + c16 * 8;
        size_t gb = (size_t)(n0 + row) * K_TOT + kc + c16 * 8;
        cpa16(sb + sw,          Ah + ga);
        cpa16(sb + 16384 + sw,  Al + ga);
        cpa16(sb + 32768 + sw,  Bh + gb);
        cpa16(sb + 49152 + sw,  Bl + gb);
    }
}

// mode 0: scatter to g_q/g_k/g_v (+bias, q*0.125). mode 1: Cout = acc + bias.
__global__ __launch_bounds__(256, 1) void hmma_gemm_kernel(
    const __nv_bfloat16* __restrict__ Ah, const __nv_bfloat16* __restrict__ Al,
    const __nv_bfloat16* __restrict__ Bh, const __nv_bfloat16* __restrict__ Bl,
    const float* __restrict__ bias, float* __restrict__ Cout, int Nt, int mode)
{
    int tid = threadIdx.x;
    int lane = tid & 31, wid = tid >> 5;
    int m0 = blockIdx.y * 128, n0 = blockIdx.x * 128;
    int warpM = (wid & 1) * 64, warpN = (wid >> 1) * 32;

    uint32_t dynb = smem_u32(gsm_raw);
    uint32_t SB = (dynb + 1023) & ~1023u;

    // ldmatrix addressing
    int g = lane >> 3, rr = lane & 7;
    int rA = (g & 1) * 8 + rr;        // 0..15
    int kbA = (g >> 1) * 16;          // 0 / 16
    uint32_t xrA = (uint32_t)((rA & 7) << 4);
    int rB = (g >> 1) * 8 + rr;       // 0..15
    int kbB = (g & 1) * 16;
    uint32_t xrB = (uint32_t)(rr << 4);

    uint32_t aRowOff = (uint32_t)(warpM + rA) * 128;
    uint32_t bRowOff = (uint32_t)(warpN + rB) * 128;

    float acc[4][4][4];
    #pragma unroll
    for (int i = 0; i < 4; i++)
        #pragma unroll
        for (int j = 0; j < 4; j++)
            #pragma unroll
            for (int q = 0; q < 4; q++) acc[i][j][q] = 0.f;

    ld_stage(SB,       Ah, Al, Bh, Bl, m0, n0, 0,  tid);
    CP_COMMIT();
    ld_stage(SB + STG, Ah, Al, Bh, Bl, m0, n0, 64, tid);
    CP_COMMIT();

    for (int c = 0; c < NCHUNK; c++) {
        CP_WAIT1();
        __syncthreads();
        uint32_t sbase = SB + (uint32_t)(c & 1) * STG;

        #pragma unroll
        for (int ks = 0; ks < 4; ks++) {
            uint32_t kterA = (uint32_t)((kbA + ks * 32)) ^ xrA;
            uint32_t kterB = (uint32_t)((kbB + ks * 32)) ^ xrB;
            uint32_t ah[4][4], alr[4][4], bh[2][4], bl[2][4];
            #pragma unroll
            for (int im = 0; im < 4; im++) {
                uint32_t ad = sbase + aRowOff + (uint32_t)(im * 2048) + kterA;
                LDSM_X4(ah[im], ad);
                LDSM_X4(alr[im], ad + 16384);
            }
            #pragma unroll
            for (int jn = 0; jn < 2; jn++) {
                uint32_t bd = sbase + 32768 + bRowOff + (uint32_t)(jn * 2048) + kterB;
                LDSM_X4(bh[jn], bd);
                LDSM_X4(bl[jn], bd + 16384);
            }
            #pragma unroll
            for (int im = 0; im < 4; im++) {
                #pragma unroll
                for (int in = 0; in < 4; in++) {
                    int jn = in >> 1, s = (in & 1) * 2;
                    MMA_BF16(acc[im][in], ah[im],  bh[jn][s], bh[jn][s + 1]);
                    MMA_BF16(acc[im][in], alr[im], bh[jn][s], bh[jn][s + 1]);
                    MMA_BF16(acc[im][in], ah[im],  bl[jn][s], bl[jn][s + 1]);
                }
            }
        }
        __syncthreads();
        if (c + 2 < NCHUNK)
            ld_stage(SB + (uint32_t)(c & 1) * STG, Ah, Al, Bh, Bl,
                     m0, n0, (c + 2) * 64, tid);
        CP_COMMIT();
    }

    // ---------------- epilogue ----------------
    int r0 = lane >> 2;              // 0..7
    int cp2 = (lane & 3) * 2;        // 0,2,4,6
    #pragma unroll
    for (int in = 0; in < 4; in++) {
        int n = n0 + warpN + in * 8 + cp2;
        float2 bs = *(const float2*)&bias[n];
        if (mode == 0) {
            int which = n >> 10, rem = n & 1023, h = rem >> 6, d = rem & 63;
            float scale = (which == 0) ? 0.125f : 1.0f;
            float* dst = (which == 0) ? g_q : (which == 1) ? g_k : g_v;
            #pragma unroll
            for (int im = 0; im < 4; im++) {
                #pragma unroll
                for (int half = 0; half < 2; half++) {
                    int m = m0 + warpM + im * 16 + r0 + half * 8;
                    int b = m >> 12, l = m & 4095;
                    float2 o;
                    o.x = (acc[im][in][half * 2 + 0] + bs.x) * scale;
                    o.y = (acc[im][in][half * 2 + 1] + bs.y) * scale;
                    *(float2*)&dst[(((size_t)(b * H_ + h)) * L_ + l) * D_ + d] = o;
                }
            }
        } else {
            #pragma unroll
            for (int im = 0; im < 4; im++) {
                #pragma unroll
                for (int half = 0; half < 2; half++) {
                    int m = m0 + warpM + im * 16 + r0 + half * 8;
                    float2 o;
                    o.x = acc[im][in][half * 2 + 0] + bs.x;
                    o.y = acc[im][in][half * 2 + 1] + bs.y;
                    *(float2*)&Cout[(size_t)m * Nt + n] = o;
                }
            }
        }
    }
}

// ---------------- neighborhood attention (fp32 in, bf16 hi/lo out) ----------------
#define LT  128
#define KVW 145
#define QW  129
#define NA_SMEM ((64 * KVW + 64 * QW) * 4)

extern __shared__ float na_sm[];

__global__ __launch_bounds__(128) void na_kernel(const float* __restrict__ rpb)
{
    float* kv = na_sm;
    float* qo = na_sm + 64 * KVW;

    int tid = threadIdx.x;
    int n0 = blockIdx.x * LT;
    int bh = blockIdx.y;
    int h = bh & (H_ - 1);

    const float* kbase = g_k + (size_t)bh * L_ * D_;
    const float* vbase = g_v + (size_t)bh * L_ * D_;
    const float* qbase = g_q + (size_t)bh * L_ * D_;

    for (int idx = tid; idx < 140 * 64; idx += 128) {
        int col = idx >> 6, d = idx & 63;
        int p = n0 - 6 + col;
        p = max(0, min(p, L_ - 1));
        kv[d * KVW + col] = kbase[(size_t)p * 64 + d];
    }
    for (int idx = tid; idx < LT * 64; idx += 128) {
        int l = idx >> 6, d = idx & 63;
        qo[d * QW + l] = qbase[(size_t)(n0 + l) * 64 + d];
    }
    __syncthreads();

    int l = tid;
    int lg = n0 + l;
    int ni = max(0, min(lg - (KNL / 2), L_ - KNL));
    int col0 = ni - (n0 - 6);

    float s[KNL];
    #pragma unroll
    for (int j = 0; j < KNL; j++) s[j] = 0.f;
    for (int d = 0; d < 64; d++) {
        float qd = qo[d * QW + l];
        const float* krow = &kv[d * KVW + col0];
        #pragma unroll
        for (int j = 0; j < KNL; j++) s[j] += qd * krow[j];
    }

    int pb = h * (2 * KNL - 1) + (ni - lg + (KNL - 1));
    float mx = -1e30f;
    #pragma unroll
    for (int j = 0; j < KNL; j++) { s[j] += rpb[pb + j]; mx = fmaxf(mx, s[j]); }
    float sum = 0.f;
    #pragma unroll
    for (int j = 0; j < KNL; j++) { s[j] = __expf(s[j] - mx); sum += s[j]; }
    float inv = 1.f / sum;
    #pragma unroll
    for (int j = 0; j < KNL; j++) s[j] *= inv;

    __syncthreads();
    for (int idx = tid; idx < 140 * 64; idx += 128) {
        int col = idx >> 6, d = idx & 63;
        int p = n0 - 6 + col;
        p = max(0, min(p, L_ - 1));
        kv[d * KVW + col] = vbase[(size_t)p * 64 + d];
    }
    __syncthreads();

    for (int d = 0; d < 64; d++) {
        const float* vrow = &kv[d * KVW + col0];
        float o = 0.f;
        #pragma unroll
        for (int j = 0; j < KNL; j++) o += s[j] * vrow[j];
        qo[d * QW + l] = o;
    }
    __syncthreads();

    int b = bh >> 4;
    size_t obase = ((size_t)b * L_ + n0) * C_ + h * 64;
    for (int idx = tid; idx < LT * 64; idx += 128) {
        int l2 = idx >> 6, d = idx & 63;
        float o = qo[d * QW + l2];
        __nv_bfloat16 hi = __float2bfloat16(o);
        __nv_bfloat16 lo = __float2bfloat16(o - __bfloat162float(hi));
        size_t oi = obase + (size_t)l2 * C_ + d;
        g_att_hi[oi] = hi;
        g_att_lo[oi] = lo;
    }
}

// ---------------- launch ----------------
extern "C" void kernel_launch(void* const* d_in, const int* in_sizes, int n_in,
                              void* d_out, int out_size)
{
    const float* x      = (const float*)d_in[0];
    const float* w_qkv  = (const float*)d_in[1];
    const float* b_qkv  = (const float*)d_in[2];
    const float* rpb    = (const float*)d_in[3];
    const float* w_proj = (const float*)d_in[4];
    const float* b_proj = (const float*)d_in[5];
    float* out = (float*)d_out;

    static bool attr_set = false;
    if (!attr_set) {
        cudaFuncSetAttribute(na_kernel, cudaFuncAttributeMaxDynamicSharedMemorySize, NA_SMEM);
        cudaFuncSetAttribute(hmma_gemm_kernel, cudaFuncAttributeMaxDynamicSharedMemorySize, GEMM_SMEM);
        attr_set = true;
    }

    __nv_bfloat16 *xh, *xl, *ath, *atl, *wqh, *wql, *wph, *wpl;
    cudaGetSymbolAddress((void**)&xh,  g_x_hi);
    cudaGetSymbolAddress((void**)&xl,  g_x_lo);
    cudaGetSymbolAddress((void**)&ath, g_att_hi);
    cudaGetSymbolAddress((void**)&atl, g_att_lo);
    cudaGetSymbolAddress((void**)&wqh, g_wqkvT_hi);
    cudaGetSymbolAddress((void**)&wql, g_wqkvT_lo);
    cudaGetSymbolAddress((void**)&wph, g_wprojT_hi);
    cudaGetSymbolAddress((void**)&wpl, g_wprojT_lo);

    // 1. split x into bf16 hi/lo
    size_t n4 = (size_t)M_TOT * K_TOT / 4;
    convert_split_kernel<<<(unsigned)((n4 + 255) / 256), 256>>>(x, xh, xl, n4);

    // 2. transpose+split weights
    transpose_split_kernel<<<dim3(3 * C_ / 32, C_ / 32), dim3(32, 32)>>>(
        w_qkv, wqh, wql, C_, 3 * C_);
    transpose_split_kernel<<<dim3(C_ / 32, C_ / 32), dim3(32, 32)>>>(
        w_proj, wph, wpl, C_, C_);

    // 3. QKV GEMM (HMMA) -> scattered q/k/v
    hmma_gemm_kernel<<<dim3(3 * C_ / 128, M_TOT / 128), 256, GEMM_SMEM>>>(
        xh, xl, wqh, wql, b_qkv, out, 3 * C_, 0);

    // 4. neighborhood attention -> att hi/lo
    na_kernel<<<dim3(L_ / LT, B_ * H_), 128, NA_SMEM>>>(rpb);

    // 5. proj GEMM -> out
    hmma_gemm_kernel<<<dim3(C_ / 128, M_TOT / 128), 256, GEMM_SMEM>>>(
        ath, atl, wph, wpl, b_proj, out, C_, 1);
}

// round 5
// speedup vs baseline: 3.7292x; 1.9784x over previous
#include <cuda_runtime.h>
#include <cuda_fp16.h>
#include <cstdint>

#define B_  4
#define L_  4096
#define H_  16
#define D_  64
#define C_  1024
#define KNL 13
#define M_TOT (B_ * L_)          // 16384
#define K_TOT C_                 // 1024

// ---------------- device scratch (no allocation allowed) ----------------
__device__ float g_q[(size_t)B_*H_*L_*D_];
__device__ float g_k[(size_t)B_*H_*L_*D_];
__device__ float g_v[(size_t)B_*H_*L_*D_];
__device__ __half g_x_hi[(size_t)M_TOT*K_TOT];
__device__ __half g_x_lo[(size_t)M_TOT*K_TOT];
__device__ __half g_att_hi[(size_t)M_TOT*K_TOT];
__device__ __half g_att_lo[(size_t)M_TOT*K_TOT];
__device__ __half g_wqkvT[(size_t)3*C_*C_];
__device__ __half g_wprojT[(size_t)C_*C_];

// ---------------- helpers ----------------
__device__ __forceinline__ uint32_t smem_u32(const void* p) {
    uint32_t a;
    asm("{ .reg .u64 t; cvta.to.shared.u64 t, %1; cvt.u32.u64 %0, t; }"
        : "=r"(a) : "l"(p));
    return a;
}
__device__ __forceinline__ void cpa16(uint32_t dst, const void* src) {
    asm volatile("cp.async.cg.shared.global [%0], [%1], 16;" :: "r"(dst), "l"(src));
}
#define CP_COMMIT() asm volatile("cp.async.commit_group;" ::: "memory")
#define CP_WAIT1()  asm volatile("cp.async.wait_group 1;" ::: "memory")

#define LDSM_X4(r, addr) \
    asm volatile("ldmatrix.sync.aligned.m8n8.x4.shared.b16 {%0,%1,%2,%3}, [%4];" \
        : "=r"((r)[0]), "=r"((r)[1]), "=r"((r)[2]), "=r"((r)[3]) : "r"(addr))

#define MMA_F16(acc, a, b0v, b1v) \
    asm volatile("mma.sync.aligned.m16n8k16.row.col.f32.f16.f16.f32 " \
        "{%0,%1,%2,%3},{%4,%5,%6,%7},{%8,%9},{%0,%1,%2,%3};" \
        : "+f"((acc)[0]), "+f"((acc)[1]), "+f"((acc)[2]), "+f"((acc)[3]) \
        : "r"((a)[0]), "r"((a)[1]), "r"((a)[2]), "r"((a)[3]), "r"(b0v), "r"(b1v))

// ---------------- conversion kernels ----------------
__global__ __launch_bounds__(256) void convert_split_kernel(
    const float* __restrict__ src, __half* __restrict__ hi,
    __half* __restrict__ lo, size_t n4)
{
    size_t i = (size_t)blockIdx.x * 256 + threadIdx.x;
    if (i >= n4) return;
    float4 v = ((const float4*)src)[i];
    float vv[4] = {v.x, v.y, v.z, v.w};
    unsigned long long ph = 0, pl = 0;
    #pragma unroll
    for (int j = 0; j < 4; j++) {
        __half h = __float2half_rn(vv[j]);
        __half l = __float2half_rn(vv[j] - __half2float(h));
        ph |= (unsigned long long)(*(unsigned short*)&h) << (16 * j);
        pl |= (unsigned long long)(*(unsigned short*)&l) << (16 * j);
    }
    ((unsigned long long*)hi)[i] = ph;
    ((unsigned long long*)lo)[i] = pl;
}

// transpose: w [K][N] fp32 -> wT [N][K] fp16
__global__ __launch_bounds__(1024) void transpose_half_kernel(
    const float* __restrict__ w, __half* __restrict__ t, int K, int N)
{
    __shared__ float sm[32][33];
    int n0 = blockIdx.x * 32, k0 = blockIdx.y * 32;
    int tx = threadIdx.x, ty = threadIdx.y;
    sm[ty][tx] = w[(size_t)(k0 + ty) * N + n0 + tx];
    __syncthreads();
    t[(size_t)(n0 + ty) * K + k0 + tx] = __float2half_rn(sm[tx][ty]);
}

// ---------------- HMMA fp16 2-product GEMM ----------------
// CTA 128x128, 8 warps (warp tile 64x32), K chunk 64, 3 stages, 1 sync/chunk.
// Stage: Ah @0 (16K) | Al @16K | Bh @32K ; stage stride 48K.
#define STG 49152
#define NSTG 3
#define GEMM_SMEM (NSTG * STG + 1024)
#define NCHUNK (K_TOT / 64)

extern __shared__ char gsm_raw[];

__device__ __forceinline__ void ld_stage(
    uint32_t sb, const __half* Ah, const __half* Al, const __half* Bh,
    int m0, int n0, int kc, int tid)
{
    #pragma unroll
    for (int i = 0; i < 4; i++) {
        int e = tid + i * 256;               // 0..1023
        int row = e >> 3, c16 = e & 7;
        uint32_t off = row * 128 + c16 * 16;
        uint32_t sw = off ^ (uint32_t)((row & 7) << 4);
        size_t ga = (size_t)(m0 + row) * K_TOT + kc + c16 * 8;
        size_t gb = (size_t)(n0 + row) * K_TOT + kc + c16 * 8;
        cpa16(sb + sw,          Ah + ga);
        cpa16(sb + 16384 + sw,  Al + ga);
        cpa16(sb + 32768 + sw,  Bh + gb);
    }
}

// mode 0: scatter to g_q/g_k/g_v (+bias, q*0.125). mode 1: Cout = acc + bias.
__global__ __launch_bounds__(256, 1) void hmma_gemm_kernel(
    const __half* __restrict__ Ah, const __half* __restrict__ Al,
    const __half* __restrict__ Bh,
    const float* __restrict__ bias, float* __restrict__ Cout, int Nt, int mode)
{
    int tid = threadIdx.x;
    int lane = tid & 31, wid = tid >> 5;
    int m0 = blockIdx.y * 128, n0 = blockIdx.x * 128;
    int warpM = (wid & 1) * 64, warpN = (wid >> 1) * 32;

    uint32_t dynb = smem_u32(gsm_raw);
    uint32_t SB = (dynb + 1023) & ~1023u;

    // ldmatrix addressing
    int g = lane >> 3, rr = lane & 7;
    int rA = (g & 1) * 8 + rr;        // 0..15
    int kbA = (g >> 1) * 16;          // 0 / 16
    uint32_t xrA = (uint32_t)((rA & 7) << 4);
    int rB = (g >> 1) * 8 + rr;       // 0..15
    int kbB = (g & 1) * 16;
    uint32_t xrB = (uint32_t)(rr << 4);

    uint32_t aRowOff = (uint32_t)(warpM + rA) * 128;
    uint32_t bRowOff = (uint32_t)(warpN + rB) * 128;

    float acc[4][4][4];
    #pragma unroll
    for (int i = 0; i < 4; i++)
        #pragma unroll
        for (int j = 0; j < 4; j++)
            #pragma unroll
            for (int q = 0; q < 4; q++) acc[i][j][q] = 0.f;

    ld_stage(SB,       Ah, Al, Bh, m0, n0, 0,  tid);
    CP_COMMIT();
    ld_stage(SB + STG, Ah, Al, Bh, m0, n0, 64, tid);
    CP_COMMIT();

    int buf = 0;
    for (int c = 0; c < NCHUNK; c++) {
        CP_WAIT1();                 // chunk c complete (<=1 group pending)
        __syncthreads();            // data visible + buffer (c+2)%3 free
        if (c + 2 < NCHUNK) {
            int nb = buf + 2; if (nb >= NSTG) nb -= NSTG;
            ld_stage(SB + (uint32_t)nb * STG, Ah, Al, Bh, m0, n0, (c + 2) * 64, tid);
        }
        CP_COMMIT();

        uint32_t sbase = SB + (uint32_t)buf * STG;
        #pragma unroll
        for (int ks = 0; ks < 4; ks++) {
            uint32_t kterA = (uint32_t)((kbA + ks * 32)) ^ xrA;
            uint32_t kterB = (uint32_t)((kbB + ks * 32)) ^ xrB;
            uint32_t ah[4][4], alr[4][4], bh[2][4];
            #pragma unroll
            for (int im = 0; im < 4; im++) {
                uint32_t ad = sbase + aRowOff + (uint32_t)(im * 2048) + kterA;
                LDSM_X4(ah[im], ad);
                LDSM_X4(alr[im], ad + 16384);
            }
            #pragma unroll
            for (int jn = 0; jn < 2; jn++) {
                uint32_t bd = sbase + 32768 + bRowOff + (uint32_t)(jn * 2048) + kterB;
                LDSM_X4(bh[jn], bd);
            }
            #pragma unroll
            for (int im = 0; im < 4; im++) {
                #pragma unroll
                for (int in = 0; in < 4; in++) {
                    int jn = in >> 1, s = (in & 1) * 2;
                    MMA_F16(acc[im][in], ah[im],  bh[jn][s], bh[jn][s + 1]);
                    MMA_F16(acc[im][in], alr[im], bh[jn][s], bh[jn][s + 1]);
                }
            }
        }
        buf++; if (buf >= NSTG) buf = 0;
    }

    // ---------------- epilogue ----------------
    int r0 = lane >> 2;              // 0..7
    int cp2 = (lane & 3) * 2;        // 0,2,4,6
    #pragma unroll
    for (int in = 0; in < 4; in++) {
        int n = n0 + warpN + in * 8 + cp2;
        float2 bs = *(const float2*)&bias[n];
        if (mode == 0) {
            int which = n >> 10, rem = n & 1023, h = rem >> 6, d = rem & 63;
            float scale = (which == 0) ? 0.125f : 1.0f;
            float* dst = (which == 0) ? g_q : (which == 1) ? g_k : g_v;
            #pragma unroll
            for (int im = 0; im < 4; im++) {
                #pragma unroll
                for (int half = 0; half < 2; half++) {
                    int m = m0 + warpM + im * 16 + r0 + half * 8;
                    int b = m >> 12, l = m & 4095;
                    float2 o;
                    o.x = (acc[im][in][half * 2 + 0] + bs.x) * scale;
                    o.y = (acc[im][in][half * 2 + 1] + bs.y) * scale;
                    *(float2*)&dst[(((size_t)(b * H_ + h)) * L_ + l) * D_ + d] = o;
                }
            }
        } else {
            #pragma unroll
            for (int im = 0; im < 4; im++) {
                #pragma unroll
                for (int half = 0; half < 2; half++) {
                    int m = m0 + warpM + im * 16 + r0 + half * 8;
                    float2 o;
                    o.x = acc[im][in][half * 2 + 0] + bs.x;
                    o.y = acc[im][in][half * 2 + 1] + bs.y;
                    *(float2*)&Cout[(size_t)m * Nt + n] = o;
                }
            }
        }
    }
}

// ---------------- neighborhood attention (fp32 in, fp16 hi/lo out) ----------------
#define LT  128
#define KVW 145
#define QW  129
#define NA_SMEM ((64 * KVW + 64 * QW) * 4)

extern __shared__ float na_sm[];

__global__ __launch_bounds__(128) void na_kernel(const float* __restrict__ rpb)
{
    float* kv = na_sm;
    float* qo = na_sm + 64 * KVW;

    int tid = threadIdx.x;
    int n0 = blockIdx.x * LT;
    int bh = blockIdx.y;
    int h = bh & (H_ - 1);

    const float* kbase = g_k + (size_t)bh * L_ * D_;
    const float* vbase = g_v + (size_t)bh * L_ * D_;
    const float* qbase = g_q + (size_t)bh * L_ * D_;

    for (int idx = tid; idx < 140 * 64; idx += 128) {
        int col = idx >> 6, d = idx & 63;
        int p = n0 - 6 + col;
        p = max(0, min(p, L_ - 1));
        kv[d * KVW + col] = kbase[(size_t)p * 64 + d];
    }
    for (int idx = tid; idx < LT * 64; idx += 128) {
        int l = idx >> 6, d = idx & 63;
        qo[d * QW + l] = qbase[(size_t)(n0 + l) * 64 + d];
    }
    __syncthreads();

    int l = tid;
    int lg = n0 + l;
    int ni = max(0, min(lg - (KNL / 2), L_ - KNL));
    int col0 = ni - (n0 - 6);

    float s[KNL];
    #pragma unroll
    for (int j = 0; j < KNL; j++) s[j] = 0.f;
    for (int d = 0; d < 64; d++) {
        float qd = qo[d * QW + l];
        const float* krow = &kv[d * KVW + col0];
        #pragma unroll
        for (int j = 0; j < KNL; j++) s[j] += qd * krow[j];
    }

    int pb = h * (2 * KNL - 1) + (ni - lg + (KNL - 1));
    float mx = -1e30f;
    #pragma unroll
    for (int j = 0; j < KNL; j++) { s[j] += rpb[pb + j]; mx = fmaxf(mx, s[j]); }
    float sum = 0.f;
    #pragma unroll
    for (int j = 0; j < KNL; j++) { s[j] = __expf(s[j] - mx); sum += s[j]; }
    float inv = 1.f / sum;
    #pragma unroll
    for (int j = 0; j < KNL; j++) s[j] *= inv;

    __syncthreads();
    for (int idx = tid; idx < 140 * 64; idx += 128) {
        int col = idx >> 6, d = idx & 63;
        int p = n0 - 6 + col;
        p = max(0, min(p, L_ - 1));
        kv[d * KVW + col] = vbase[(size_t)p * 64 + d];
    }
    __syncthreads();

    for (int d = 0; d < 64; d++) {
        const float* vrow = &kv[d * KVW + col0];
        float o = 0.f;
        #pragma unroll
        for (int j = 0; j < KNL; j++) o += s[j] * vrow[j];
        qo[d * QW + l] = o;
    }
    __syncthreads();

    int b = bh >> 4;
    size_t obase = ((size_t)b * L_ + n0) * C_ + h * 64;
    for (int idx = tid; idx < LT * 64; idx += 128) {
        int l2 = idx >> 6, d = idx & 63;
        float o = qo[d * QW + l2];
        __half hi = __float2half_rn(o);
        __half lo = __float2half_rn(o - __half2float(hi));
        size_t oi = obase + (size_t)l2 * C_ + d;
        g_att_hi[oi] = hi;
        g_att_lo[oi] = lo;
    }
}

// ---------------- launch ----------------
extern "C" void kernel_launch(void* const* d_in, const int* in_sizes, int n_in,
                              void* d_out, int out_size)
{
    const float* x      = (const float*)d_in[0];
    const float* w_qkv  = (const float*)d_in[1];
    const float* b_qkv  = (const float*)d_in[2];
    const float* rpb    = (const float*)d_in[3];
    const float* w_proj = (const float*)d_in[4];
    const float* b_proj = (const float*)d_in[5];
    float* out = (float*)d_out;

    static bool attr_set = false;
    if (!attr_set) {
        cudaFuncSetAttribute(na_kernel, cudaFuncAttributeMaxDynamicSharedMemorySize, NA_SMEM);
        cudaFuncSetAttribute(hmma_gemm_kernel, cudaFuncAttributeMaxDynamicSharedMemorySize, GEMM_SMEM);
        attr_set = true;
    }

    __half *xh, *xl, *ath, *atl, *wq, *wp;
    cudaGetSymbolAddress((void**)&xh,  g_x_hi);
    cudaGetSymbolAddress((void**)&xl,  g_x_lo);
    cudaGetSymbolAddress((void**)&ath, g_att_hi);
    cudaGetSymbolAddress((void**)&atl, g_att_lo);
    cudaGetSymbolAddress((void**)&wq,  g_wqkvT);
    cudaGetSymbolAddress((void**)&wp,  g_wprojT);

    // 1. split x into fp16 hi/lo
    size_t n4 = (size_t)M_TOT * K_TOT / 4;
    convert_split_kernel<<<(unsigned)((n4 + 255) / 256), 256>>>(x, xh, xl, n4);

    // 2. transpose weights to fp16 [N][K]
    transpose_half_kernel<<<dim3(3 * C_ / 32, C_ / 32), dim3(32, 32)>>>(
        w_qkv, wq, C_, 3 * C_);
    transpose_half_kernel<<<dim3(C_ / 32, C_ / 32), dim3(32, 32)>>>(
        w_proj, wp, C_, C_);

    // 3. QKV GEMM (HMMA fp16 2-product) -> scattered q/k/v
    hmma_gemm_kernel<<<dim3(3 * C_ / 128, M_TOT / 128), 256, GEMM_SMEM>>>(
        xh, xl, wq, b_qkv, out, 3 * C_, 0);

    // 4. neighborhood attention -> att hi/lo (fp16)
    na_kernel<<<dim3(L_ / LT, B_ * H_), 128, NA_SMEM>>>(rpb);

    // 5. proj GEMM -> out
    hmma_gemm_kernel<<<dim3(C_ / 128, M_TOT / 128), 256, GEMM_SMEM>>>(
        ath, atl, wp, b_proj, out, C_, 1);
}

// round 6
// speedup vs baseline: 3.7970x; 1.0182x over previous
#include <cuda_runtime.h>
#include <cuda_fp16.h>
#include <cstdint>

#define B_  4
#define L_  4096
#define H_  16
#define D_  64
#define C_  1024
#define KNL 13
#define M_TOT (B_ * L_)          // 16384
#define K_TOT C_                 // 1024

// ---------------- device scratch (no allocation allowed) ----------------
__device__ float g_q[(size_t)B_*H_*L_*D_];
__device__ float g_k[(size_t)B_*H_*L_*D_];
__device__ float g_v[(size_t)B_*H_*L_*D_];
__device__ __half g_x_hi[(size_t)M_TOT*K_TOT];
__device__ __half g_x_lo[(size_t)M_TOT*K_TOT];
__device__ __half g_att_hi[(size_t)M_TOT*K_TOT];
__device__ __half g_att_lo[(size_t)M_TOT*K_TOT];
__device__ __half g_wqkvT[(size_t)3*C_*C_];
__device__ __half g_wprojT[(size_t)C_*C_];

// ---------------- helpers ----------------
__device__ __forceinline__ uint32_t smem_u32(const void* p) {
    uint32_t a;
    asm("{ .reg .u64 t; cvta.to.shared.u64 t, %1; cvt.u32.u64 %0, t; }"
        : "=r"(a) : "l"(p));
    return a;
}
__device__ __forceinline__ void cpa16(uint32_t dst, const void* src) {
    asm volatile("cp.async.cg.shared.global [%0], [%1], 16;" :: "r"(dst), "l"(src));
}
#define CP_COMMIT() asm volatile("cp.async.commit_group;" ::: "memory")
#define CP_WAIT1()  asm volatile("cp.async.wait_group 1;" ::: "memory")

#define LDSM_X4(r, addr) \
    asm volatile("ldmatrix.sync.aligned.m8n8.x4.shared.b16 {%0,%1,%2,%3}, [%4];" \
        : "=r"((r)[0]), "=r"((r)[1]), "=r"((r)[2]), "=r"((r)[3]) : "r"(addr))

#define MMA_F16(acc, a, b0v, b1v) \
    asm volatile("mma.sync.aligned.m16n8k16.row.col.f32.f16.f16.f32 " \
        "{%0,%1,%2,%3},{%4,%5,%6,%7},{%8,%9},{%0,%1,%2,%3};" \
        : "+f"((acc)[0]), "+f"((acc)[1]), "+f"((acc)[2]), "+f"((acc)[3]) \
        : "r"((a)[0]), "r"((a)[1]), "r"((a)[2]), "r"((a)[3]), "r"(b0v), "r"(b1v))

// ---------------- conversion kernels ----------------
__global__ __launch_bounds__(256) void convert_split_kernel(
    const float* __restrict__ src, __half* __restrict__ hi,
    __half* __restrict__ lo, size_t n4)
{
    size_t i = (size_t)blockIdx.x * 256 + threadIdx.x;
    if (i >= n4) return;
    float4 v = ((const float4*)src)[i];
    float vv[4] = {v.x, v.y, v.z, v.w};
    unsigned long long ph = 0, pl = 0;
    #pragma unroll
    for (int j = 0; j < 4; j++) {
        __half h = __float2half_rn(vv[j]);
        __half l = __float2half_rn(vv[j] - __half2float(h));
        ph |= (unsigned long long)(*(unsigned short*)&h) << (16 * j);
        pl |= (unsigned long long)(*(unsigned short*)&l) << (16 * j);
    }
    ((unsigned long long*)hi)[i] = ph;
    ((unsigned long long*)lo)[i] = pl;
}

// transpose: w [K][N] fp32 -> wT [N][K] fp16
__global__ __launch_bounds__(1024) void transpose_half_kernel(
    const float* __restrict__ w, __half* __restrict__ t, int K, int N)
{
    __shared__ float sm[32][33];
    int n0 = blockIdx.x * 32, k0 = blockIdx.y * 32;
    int tx = threadIdx.x, ty = threadIdx.y;
    sm[ty][tx] = w[(size_t)(k0 + ty) * N + n0 + tx];
    __syncthreads();
    t[(size_t)(n0 + ty) * K + k0 + tx] = __float2half_rn(sm[tx][ty]);
}

// ---------------- HMMA fp16 2-product GEMM ----------------
// CTA 128(M) x 256(N), 512 threads = 16 warps (2M x 8N), warp tile 64x32.
// K chunk 64, 3 stages, 1 sync/chunk.
// Stage: Ah @0 (16K) | Al @16K | Bh @32K (32K) ; stage stride 64K.
#define STG 65536
#define NSTG 3
#define GEMM_SMEM (NSTG * STG + 1024)
#define NCHUNK (K_TOT / 64)

extern __shared__ char gsm_raw[];

__device__ __forceinline__ void ld_stage(
    uint32_t sb, const __half* Ah, const __half* Al, const __half* Bh,
    int m0, int n0, int kc, int tid)
{
    // A: 128 rows x 8 lines (hi+lo)
    #pragma unroll
    for (int i = 0; i < 2; i++) {
        int e = tid + i * 512;               // 0..1023
        int row = e >> 3, c16 = e & 7;
        uint32_t off = row * 128 + c16 * 16;
        uint32_t sw = off ^ (uint32_t)((row & 7) << 4);
        size_t ga = (size_t)(m0 + row) * K_TOT + kc + c16 * 8;
        cpa16(sb + sw,          Ah + ga);
        cpa16(sb + 16384 + sw,  Al + ga);
    }
    // B: 256 rows x 8 lines
    #pragma unroll
    for (int i = 0; i < 4; i++) {
        int e = tid + i * 512;               // 0..2047
        int row = e >> 3, c16 = e & 7;
        uint32_t off = row * 128 + c16 * 16;
        uint32_t sw = off ^ (uint32_t)((row & 7) << 4);
        size_t gb = (size_t)(n0 + row) * K_TOT + kc + c16 * 8;
        cpa16(sb + 32768 + sw,  Bh + gb);
    }
}

// mode 0: scatter to g_q/g_k/g_v (+bias, q*0.125). mode 1: Cout = acc + bias.
__global__ __launch_bounds__(512, 1) void hmma_gemm_kernel(
    const __half* __restrict__ Ah, const __half* __restrict__ Al,
    const __half* __restrict__ Bh,
    const float* __restrict__ bias, float* __restrict__ Cout, int Nt, int mode)
{
    int tid = threadIdx.x;
    int lane = tid & 31, wid = tid >> 5;
    int m0 = blockIdx.y * 128, n0 = blockIdx.x * 256;
    int warpM = (wid & 1) * 64, warpN = (wid >> 1) * 32;

    uint32_t dynb = smem_u32(gsm_raw);
    uint32_t SB = (dynb + 1023) & ~1023u;

    // ldmatrix addressing
    int g = lane >> 3, rr = lane & 7;
    int rA = (g & 1) * 8 + rr;        // 0..15
    int kbA = (g >> 1) * 16;          // 0 / 16
    uint32_t xrA = (uint32_t)((rA & 7) << 4);
    int rB = (g >> 1) * 8 + rr;       // 0..15
    int kbB = (g & 1) * 16;
    uint32_t xrB = (uint32_t)(rr << 4);

    uint32_t aRowOff = (uint32_t)(warpM + rA) * 128;
    uint32_t bRowOff = (uint32_t)(warpN + rB) * 128;

    float acc[4][4][4];
    #pragma unroll
    for (int i = 0; i < 4; i++)
        #pragma unroll
        for (int j = 0; j < 4; j++)
            #pragma unroll
            for (int q = 0; q < 4; q++) acc[i][j][q] = 0.f;

    ld_stage(SB,       Ah, Al, Bh, m0, n0, 0,  tid);
    CP_COMMIT();
    ld_stage(SB + STG, Ah, Al, Bh, m0, n0, 64, tid);
    CP_COMMIT();

    int buf = 0;
    for (int c = 0; c < NCHUNK; c++) {
        CP_WAIT1();                 // chunk c complete (<=1 group pending)
        __syncthreads();            // data visible + buffer (c+2)%3 free
        if (c + 2 < NCHUNK) {
            int nb = buf + 2; if (nb >= NSTG) nb -= NSTG;
            ld_stage(SB + (uint32_t)nb * STG, Ah, Al, Bh, m0, n0, (c + 2) * 64, tid);
        }
        CP_COMMIT();

        uint32_t sbase = SB + (uint32_t)buf * STG;
        #pragma unroll
        for (int ks = 0; ks < 4; ks++) {
            uint32_t kterA = (uint32_t)((kbA + ks * 32)) ^ xrA;
            uint32_t kterB = (uint32_t)((kbB + ks * 32)) ^ xrB;
            uint32_t bh[2][4];
            #pragma unroll
            for (int jn = 0; jn < 2; jn++) {
                uint32_t bd = sbase + 32768 + bRowOff + (uint32_t)(jn * 2048) + kterB;
                LDSM_X4(bh[jn], bd);
            }
            // keep only one A hi/lo pair live at a time -> fits 128 regs
            #pragma unroll
            for (int im = 0; im < 4; im++) {
                uint32_t ah[4], alr[4];
                uint32_t ad = sbase + aRowOff + (uint32_t)(im * 2048) + kterA;
                LDSM_X4(ah, ad);
                LDSM_X4(alr, ad + 16384);
                #pragma unroll
                for (int in = 0; in < 4; in++) {
                    int jn = in >> 1, s = (in & 1) * 2;
                    MMA_F16(acc[im][in], ah,  bh[jn][s], bh[jn][s + 1]);
                    MMA_F16(acc[im][in], alr, bh[jn][s], bh[jn][s + 1]);
                }
            }
        }
        buf++; if (buf >= NSTG) buf = 0;
    }

    // ---------------- epilogue ----------------
    int r0 = lane >> 2;              // 0..7
    int cp2 = (lane & 3) * 2;        // 0,2,4,6
    #pragma unroll
    for (int in = 0; in < 4; in++) {
        int n = n0 + warpN + in * 8 + cp2;
        float2 bs = *(const float2*)&bias[n];
        if (mode == 0) {
            int which = n >> 10, rem = n & 1023, h = rem >> 6, d = rem & 63;
            float scale = (which == 0) ? 0.125f : 1.0f;
            float* dst = (which == 0) ? g_q : (which == 1) ? g_k : g_v;
            #pragma unroll
            for (int im = 0; im < 4; im++) {
                #pragma unroll
                for (int half = 0; half < 2; half++) {
                    int m = m0 + warpM + im * 16 + r0 + half * 8;
                    int b = m >> 12, l = m & 4095;
                    float2 o;
                    o.x = (acc[im][in][half * 2 + 0] + bs.x) * scale;
                    o.y = (acc[im][in][half * 2 + 1] + bs.y) * scale;
                    *(float2*)&dst[(((size_t)(b * H_ + h)) * L_ + l) * D_ + d] = o;
                }
            }
        } else {
            #pragma unroll
            for (int im = 0; im < 4; im++) {
                #pragma unroll
                for (int half = 0; half < 2; half++) {
                    int m = m0 + warpM + im * 16 + r0 + half * 8;
                    float2 o;
                    o.x = acc[im][in][half * 2 + 0] + bs.x;
                    o.y = acc[im][in][half * 2 + 1] + bs.y;
                    *(float2*)&Cout[(size_t)m * Nt + n] = o;
                }
            }
        }
    }
}

// ---------------- neighborhood attention (fp32 in, fp16 hi/lo out) ----------------
#define LT  128
#define KVW 145
#define QW  129
#define NA_SMEM ((64 * KVW + 64 * QW) * 4)

extern __shared__ float na_sm[];

__global__ __launch_bounds__(128) void na_kernel(const float* __restrict__ rpb)
{
    float* kv = na_sm;
    float* qo = na_sm + 64 * KVW;

    int tid = threadIdx.x;
    int n0 = blockIdx.x * LT;
    int bh = blockIdx.y;
    int h = bh & (H_ - 1);

    const float* kbase = g_k + (size_t)bh * L_ * D_;
    const float* vbase = g_v + (size_t)bh * L_ * D_;
    const float* qbase = g_q + (size_t)bh * L_ * D_;

    for (int idx = tid; idx < 140 * 64; idx += 128) {
        int col = idx >> 6, d = idx & 63;
        int p = n0 - 6 + col;
        p = max(0, min(p, L_ - 1));
        kv[d * KVW + col] = kbase[(size_t)p * 64 + d];
    }
    for (int idx = tid; idx < LT * 64; idx += 128) {
        int l = idx >> 6, d = idx & 63;
        qo[d * QW + l] = qbase[(size_t)(n0 + l) * 64 + d];
    }
    __syncthreads();

    int l = tid;
    int lg = n0 + l;
    int ni = max(0, min(lg - (KNL / 2), L_ - KNL));
    int col0 = ni - (n0 - 6);

    float s[KNL];
    #pragma unroll
    for (int j = 0; j < KNL; j++) s[j] = 0.f;
    for (int d = 0; d < 64; d++) {
        float qd = qo[d * QW + l];
        const float* krow = &kv[d * KVW + col0];
        #pragma unroll
        for (int j = 0; j < KNL; j++) s[j] += qd * krow[j];
    }

    int pb = h * (2 * KNL - 1) + (ni - lg + (KNL - 1));
    float mx = -1e30f;
    #pragma unroll
    for (int j = 0; j < KNL; j++) { s[j] += rpb[pb + j]; mx = fmaxf(mx, s[j]); }
    float sum = 0.f;
    #pragma unroll
    for (int j = 0; j < KNL; j++) { s[j] = __expf(s[j] - mx); sum += s[j]; }
    float inv = 1.f / sum;
    #pragma unroll
    for (int j = 0; j < KNL; j++) s[j] *= inv;

    __syncthreads();
    for (int idx = tid; idx < 140 * 64; idx += 128) {
        int col = idx >> 6, d = idx & 63;
        int p = n0 - 6 + col;
        p = max(0, min(p, L_ - 1));
        kv[d * KVW + col] = vbase[(size_t)p * 64 + d];
    }
    __syncthreads();

    for (int d = 0; d < 64; d++) {
        const float* vrow = &kv[d * KVW + col0];
        float o = 0.f;
        #pragma unroll
        for (int j = 0; j < KNL; j++) o += s[j] * vrow[j];
        qo[d * QW + l] = o;
    }
    __syncthreads();

    int b = bh >> 4;
    size_t obase = ((size_t)b * L_ + n0) * C_ + h * 64;
    for (int idx = tid; idx < LT * 64; idx += 128) {
        int l2 = idx >> 6, d = idx & 63;
        float o = qo[d * QW + l2];
        __half hi = __float2half_rn(o);
        __half lo = __float2half_rn(o - __half2float(hi));
        size_t oi = obase + (size_t)l2 * C_ + d;
        g_att_hi[oi] = hi;
        g_att_lo[oi] = lo;
    }
}

// ---------------- launch ----------------
extern "C" void kernel_launch(void* const* d_in, const int* in_sizes, int n_in,
                              void* d_out, int out_size)
{
    const float* x      = (const float*)d_in[0];
    const float* w_qkv  = (const float*)d_in[1];
    const float* b_qkv  = (const float*)d_in[2];
    const float* rpb    = (const float*)d_in[3];
    const float* w_proj = (const float*)d_in[4];
    const float* b_proj = (const float*)d_in[5];
    float* out = (float*)d_out;

    static bool attr_set = false;
    if (!attr_set) {
        cudaFuncSetAttribute(na_kernel, cudaFuncAttributeMaxDynamicSharedMemorySize, NA_SMEM);
        cudaFuncSetAttribute(hmma_gemm_kernel, cudaFuncAttributeMaxDynamicSharedMemorySize, GEMM_SMEM);
        attr_set = true;
    }

    __half *xh, *xl, *ath, *atl, *wq, *wp;
    cudaGetSymbolAddress((void**)&xh,  g_x_hi);
    cudaGetSymbolAddress((void**)&xl,  g_x_lo);
    cudaGetSymbolAddress((void**)&ath, g_att_hi);
    cudaGetSymbolAddress((void**)&atl, g_att_lo);
    cudaGetSymbolAddress((void**)&wq,  g_wqkvT);
    cudaGetSymbolAddress((void**)&wp,  g_wprojT);

    // 1. split x into fp16 hi/lo
    size_t n4 = (size_t)M_TOT * K_TOT / 4;
    convert_split_kernel<<<(unsigned)((n4 + 255) / 256), 256>>>(x, xh, xl, n4);

    // 2. transpose weights to fp16 [N][K]
    transpose_half_kernel<<<dim3(3 * C_ / 32, C_ / 32), dim3(32, 32)>>>(
        w_qkv, wq, C_, 3 * C_);
    transpose_half_kernel<<<dim3(C_ / 32, C_ / 32), dim3(32, 32)>>>(
        w_proj, wp, C_, C_);

    // 3. QKV GEMM (HMMA fp16 2-product) -> scattered q/k/v
    hmma_gemm_kernel<<<dim3(3 * C_ / 256, M_TOT / 128), 512, GEMM_SMEM>>>(
        xh, xl, wq, b_qkv, out, 3 * C_, 0);

    // 4. neighborhood attention -> att hi/lo (fp16)
    na_kernel<<<dim3(L_ / LT, B_ * H_), 128, NA_SMEM>>>(rpb);

    // 5. proj GEMM -> out
    hmma_gemm_kernel<<<dim3(C_ / 256, M_TOT / 128), 512, GEMM_SMEM>>>(
        ath, atl, wp, b_proj, out, C_, 1);
}

// round 9
// speedup vs baseline: 5.4586x; 1.4376x over previous
#include <cuda_runtime.h>
#include <cuda_fp16.h>
#include <cuda.h>
#include <cstdint>

#define B_  4
#define L_  4096
#define H_  16
#define D_  64
#define C_  1024
#define KNL 13
#define M_TOT (B_ * L_)          // 16384
#define K_TOT C_                 // 1024

// ---------------- device scratch (no allocation allowed) ----------------
__device__ float g_q[(size_t)B_*H_*L_*D_];
__device__ float g_k[(size_t)B_*H_*L_*D_];
__device__ float g_v[(size_t)B_*H_*L_*D_];
__device__ __half g_x_h[(size_t)M_TOT*K_TOT];
__device__ __half g_att_h[(size_t)M_TOT*K_TOT];
__device__ __half g_wqkvT[(size_t)3*C_*C_];
__device__ __half g_wprojT[(size_t)C_*C_];

// ---------------- helpers ----------------
__device__ __forceinline__ uint32_t smem_u32(const void* p) {
    uint32_t a;
    asm("{ .reg .u64 t; cvta.to.shared.u64 t, %1; cvt.u32.u64 %0, t; }"
        : "=r"(a) : "l"(p));
    return a;
}
#define MBARRIER_INIT(addr, cnt) \
    asm volatile("mbarrier.init.shared.b64 [%0], %1;" :: "r"(addr), "r"(cnt) : "memory")
#define MBARRIER_EXPECT_TX(addr, bytes) \
    asm volatile("mbarrier.arrive.expect_tx.shared.b64 _, [%0], %1;" \
                 :: "r"(addr), "r"((uint32_t)(bytes)) : "memory")
// bounded wait: never hangs the GPU; a stuck TMA becomes a wrong answer.
__device__ __forceinline__ void mbar_wait(uint32_t mbar, uint32_t parity) {
    for (int it = 0; it < 65536; it++) {
        uint32_t done;
        asm volatile("{\n\t.reg .pred p;\n\t"
            "mbarrier.try_wait.parity.acquire.cta.shared::cta.b64 p, [%1], %2, 0x2710;\n\t"
            "selp.b32 %0, 1, 0, p;\n\t}"
            : "=r"(done) : "r"(mbar), "r"(parity) : "memory");
        if (done) return;
    }
}
#define FENCE_PROXY_ASYNC() asm volatile("fence.proxy.async.shared::cta;" ::: "memory")

__device__ __forceinline__ void tma2d(uint32_t dst, const void* map,
                                      int cx, int cy, uint32_t mbar) {
    asm volatile(
        "cp.async.bulk.tensor.2d.shared::cta.global.tile.mbarrier::complete_tx::bytes "
        "[%0], [%1, {%2, %3}], [%4];"
        :: "r"(dst), "l"(map), "r"(cx), "r"(cy), "r"(mbar) : "memory");
}

__device__ __forceinline__ void cpa16(uint32_t dst, const void* src) {
    asm volatile("cp.async.cg.shared.global [%0], [%1], 16;" :: "r"(dst), "l"(src));
}
#define CP_COMMIT() asm volatile("cp.async.commit_group;" ::: "memory")
#define CP_WAIT1()  asm volatile("cp.async.wait_group 1;" ::: "memory")

#define LDSM_X4(r, addr) \
    asm volatile("ldmatrix.sync.aligned.m8n8.x4.shared.b16 {%0,%1,%2,%3}, [%4];" \
        : "=r"((r)[0]), "=r"((r)[1]), "=r"((r)[2]), "=r"((r)[3]) : "r"(addr))

#define MMA_F16(acc, a, b0v, b1v) \
    asm volatile("mma.sync.aligned.m16n8k16.row.col.f32.f16.f16.f32 " \
        "{%0,%1,%2,%3},{%4,%5,%6,%7},{%8,%9},{%0,%1,%2,%3};" \
        : "+f"((acc)[0]), "+f"((acc)[1]), "+f"((acc)[2]), "+f"((acc)[3]) \
        : "r"((a)[0]), "r"((a)[1]), "r"((a)[2]), "r"((a)[3]), "r"(b0v), "r"(b1v))

// ---------------- conversion kernels ----------------
__global__ __launch_bounds__(256) void convert_half_kernel(
    const float* __restrict__ src, __half* __restrict__ dst, size_t n4)
{
    size_t i = (size_t)blockIdx.x * 256 + threadIdx.x;
    if (i >= n4) return;
    float4 v = ((const float4*)src)[i];
    __half2 a = __floats2half2_rn(v.x, v.y);
    __half2 b = __floats2half2_rn(v.z, v.w);
    ((uint2*)dst)[i] = make_uint2(*(uint32_t*)&a, *(uint32_t*)&b);
}

__global__ __launch_bounds__(1024) void transpose_half_kernel(
    const float* __restrict__ w, __half* __restrict__ t, int K, int N)
{
    __shared__ float sm[32][33];
    int n0 = blockIdx.x * 32, k0 = blockIdx.y * 32;
    int tx = threadIdx.x, ty = threadIdx.y;
    sm[ty][tx] = w[(size_t)(k0 + ty) * N + n0 + tx];
    __syncthreads();
    t[(size_t)(n0 + ty) * K + k0 + tx] = __float2half_rn(sm[tx][ty]);
}

// ---------------- shared GEMM config ----------------
// CTA 128(M) x 256(N), 512 threads = 16 warps (2M x 8N), warp tile 64x32.
// Stage: A (128x64 fp16, 16K) @0 | B (256x64 fp16, 32K) @16K ; stride 48K.
#define STG 49152
#define NSTG_TMA 4
#define NSTG_CPA 3
#define GEMM_SMEM_TMA (NSTG_TMA * STG + 1024)
#define GEMM_SMEM_CPA (NSTG_CPA * STG + 1024)
#define NCHUNK (K_TOT / 64)

extern __shared__ char gsm_raw[];

struct FragCtx {
    uint32_t xrA, xrB, aRowOff, bRowOff;
    int kbA, kbB;
};
__device__ __forceinline__ FragCtx frag_ctx(int lane, int warpM, int warpN) {
    FragCtx f;
    int g = lane >> 3, rr = lane & 7;
    int rA = (g & 1) * 8 + rr;
    f.kbA = (g >> 1) * 16;
    f.xrA = (uint32_t)((rA & 7) << 4);
    int rB = (g >> 1) * 8 + rr;
    f.kbB = (g & 1) * 16;
    f.xrB = (uint32_t)(rr << 4);
    f.aRowOff = (uint32_t)(warpM + rA) * 128;
    f.bRowOff = (uint32_t)(warpN + rB) * 128;
    return f;
}

__device__ __forceinline__ void compute_chunk(
    uint32_t sbase, const FragCtx& f, float acc[4][4][4])
{
    #pragma unroll
    for (int ks = 0; ks < 4; ks++) {
        uint32_t kterA = (uint32_t)((f.kbA + ks * 32)) ^ f.xrA;
        uint32_t kterB = (uint32_t)((f.kbB + ks * 32)) ^ f.xrB;
        uint32_t bh[2][4];
        #pragma unroll
        for (int jn = 0; jn < 2; jn++) {
            uint32_t bd = sbase + 16384 + f.bRowOff + (uint32_t)(jn * 2048) + kterB;
            LDSM_X4(bh[jn], bd);
        }
        #pragma unroll
        for (int im = 0; im < 4; im++) {
            uint32_t ah[4];
            uint32_t ad = sbase + f.aRowOff + (uint32_t)(im * 2048) + kterA;
            LDSM_X4(ah, ad);
            #pragma unroll
            for (int in = 0; in < 4; in++) {
                int jn = in >> 1, s = (in & 1) * 2;
                MMA_F16(acc[im][in], ah, bh[jn][s], bh[jn][s + 1]);
            }
        }
    }
}

__device__ __forceinline__ void gemm_epilogue(
    float acc[4][4][4], const float* bias, float* Cout,
    int m0, int n0, int warpM, int warpN, int lane, int Nt, int mode)
{
    int r0 = lane >> 2;
    int cp2 = (lane & 3) * 2;
    #pragma unroll
    for (int in = 0; in < 4; in++) {
        int n = n0 + warpN + in * 8 + cp2;
        float2 bs = *(const float2*)&bias[n];
        if (mode == 0) {
            int which = n >> 10, rem = n & 1023, h = rem >> 6, d = rem & 63;
            float scale = (which == 0) ? 0.125f : 1.0f;
            float* dst = (which == 0) ? g_q : (which == 1) ? g_k : g_v;
            #pragma unroll
            for (int im = 0; im < 4; im++) {
                #pragma unroll
                for (int half = 0; half < 2; half++) {
                    int m = m0 + warpM + im * 16 + r0 + half * 8;
                    int b = m >> 12, l = m & 4095;
                    float2 o;
                    o.x = (acc[im][in][half * 2 + 0] + bs.x) * scale;
                    o.y = (acc[im][in][half * 2 + 1] + bs.y) * scale;
                    *(float2*)&dst[(((size_t)(b * H_ + h)) * L_ + l) * D_ + d] = o;
                }
            }
        } else {
            #pragma unroll
            for (int im = 0; im < 4; im++) {
                #pragma unroll
                for (int half = 0; half < 2; half++) {
                    int m = m0 + warpM + im * 16 + r0 + half * 8;
                    float2 o;
                    o.x = acc[im][in][half * 2 + 0] + bs.x;
                    o.y = acc[im][in][half * 2 + 1] + bs.y;
                    *(float2*)&Cout[(size_t)m * Nt + n] = o;
                }
            }
        }
    }
}

// ---------------- TMA GEMM ----------------
__global__ __launch_bounds__(512, 1) void tma_gemm_kernel(
    const __grid_constant__ CUtensorMap mapA,
    const __grid_constant__ CUtensorMap mapB,
    const float* __restrict__ bias, float* __restrict__ Cout, int Nt, int mode)
{
    __shared__ __align__(8) unsigned long long s_mbar[NSTG_TMA];

    int tid = threadIdx.x;
    int lane = tid & 31, wid = tid >> 5;
    int m0 = blockIdx.y * 128, n0 = blockIdx.x * 256;
    int warpM = (wid & 1) * 64, warpN = (wid >> 1) * 32;

    uint32_t dynb = smem_u32(gsm_raw);
    uint32_t SB = (dynb + 1023) & ~1023u;

    if (tid == 0) {
        #pragma unroll
        for (int s = 0; s < NSTG_TMA; s++) MBARRIER_INIT(smem_u32(&s_mbar[s]), 1);
        FENCE_PROXY_ASYNC();
    }
    __syncthreads();

    if (tid == 0) {
        #pragma unroll
        for (int p = 0; p < NSTG_TMA - 1; p++) {
            uint32_t mb = smem_u32(&s_mbar[p]);
            uint32_t dst = SB + (uint32_t)p * STG;
            MBARRIER_EXPECT_TX(mb, STG);
            tma2d(dst,         &mapA, p * 64, m0, mb);
            tma2d(dst + 16384, &mapB, p * 64, n0, mb);
        }
    }

    FragCtx f = frag_ctx(lane, warpM, warpN);

    float acc[4][4][4];
    #pragma unroll
    for (int i = 0; i < 4; i++)
        #pragma unroll
        for (int j = 0; j < 4; j++)
            #pragma unroll
            for (int q = 0; q < 4; q++) acc[i][j][q] = 0.f;

    for (int c = 0; c < NCHUNK; c++) {
        if (tid == 0 && c + NSTG_TMA - 1 < NCHUNK) {
            int p = c + NSTG_TMA - 1, b = p % NSTG_TMA;
            uint32_t mb = smem_u32(&s_mbar[b]);
            uint32_t dst = SB + (uint32_t)b * STG;
            MBARRIER_EXPECT_TX(mb, STG);
            tma2d(dst,         &mapA, p * 64, m0, mb);
            tma2d(dst + 16384, &mapB, p * 64, n0, mb);
        }
        int buf = c & (NSTG_TMA - 1);
        mbar_wait(smem_u32(&s_mbar[buf]), (c / NSTG_TMA) & 1);
        compute_chunk(SB + (uint32_t)buf * STG, f, acc);
        __syncthreads();
    }

    gemm_epilogue(acc, bias, Cout, m0, n0, warpM, warpN, lane, Nt, mode);
}

// ---------------- cp.async fallback GEMM ----------------
__device__ __forceinline__ void ld_stage_cpa(
    uint32_t sb, const __half* Ah, const __half* Bh,
    int m0, int n0, int kc, int tid)
{
    {
        int e = tid;                          // 0..511 : A 128 rows x 8 lines
        int row = e >> 2, c16 = (e & 3) * 2;  // two lines per thread
        uint32_t off = row * 128 + c16 * 16;
        uint32_t sw0 = off ^ (uint32_t)((row & 7) << 4);
        uint32_t sw1 = (off + 16) ^ (uint32_t)((row & 7) << 4);
        size_t ga = (size_t)(m0 + row) * K_TOT + kc + c16 * 8;
        cpa16(sb + sw0, Ah + ga);
        cpa16(sb + sw1, Ah + ga + 8);
    }
    #pragma unroll
    for (int i = 0; i < 4; i++) {             // B: 256 rows x 8 lines
        int e = tid + i * 512;
        int row = e >> 3, c16 = e & 7;
        uint32_t off = row * 128 + c16 * 16;
        uint32_t sw = off ^ (uint32_t)((row & 7) << 4);
        size_t gb = (size_t)(n0 + row) * K_TOT + kc + c16 * 8;
        cpa16(sb + 16384 + sw, Bh + gb);
    }
}

__global__ __launch_bounds__(512, 1) void cpa_gemm_kernel(
    const __half* __restrict__ Ah, const __half* __restrict__ Bh,
    const float* __restrict__ bias, float* __restrict__ Cout, int Nt, int mode)
{
    int tid = threadIdx.x;
    int lane = tid & 31, wid = tid >> 5;
    int m0 = blockIdx.y * 128, n0 = blockIdx.x * 256;
    int warpM = (wid & 1) * 64, warpN = (wid >> 1) * 32;

    uint32_t dynb = smem_u32(gsm_raw);
    uint32_t SB = (dynb + 1023) & ~1023u;

    FragCtx f = frag_ctx(lane, warpM, warpN);

    float acc[4][4][4];
    #pragma unroll
    for (int i = 0; i < 4; i++)
        #pragma unroll
        for (int j = 0; j < 4; j++)
            #pragma unroll
            for (int q = 0; q < 4; q++) acc[i][j][q] = 0.f;

    ld_stage_cpa(SB,       Ah, Bh, m0, n0, 0,  tid);
    CP_COMMIT();
    ld_stage_cpa(SB + STG, Ah, Bh, m0, n0, 64, tid);
    CP_COMMIT();

    int buf = 0;
    for (int c = 0; c < NCHUNK; c++) {
        CP_WAIT1();
        __syncthreads();
        if (c + 2 < NCHUNK) {
            int nb = buf + 2; if (nb >= NSTG_CPA) nb -= NSTG_CPA;
            ld_stage_cpa(SB + (uint32_t)nb * STG, Ah, Bh, m0, n0, (c + 2) * 64, tid);
        }
        CP_COMMIT();
        compute_chunk(SB + (uint32_t)buf * STG, f, acc);
        buf++; if (buf >= NSTG_CPA) buf = 0;
    }

    gemm_epilogue(acc, bias, Cout, m0, n0, warpM, warpN, lane, Nt, mode);
}

// ---------------- neighborhood attention ----------------
#define LT  128
#define KVW 145
#define QW  129
#define NA_SMEM ((64 * KVW + 64 * QW) * 4)

extern __shared__ float na_sm[];

__global__ __launch_bounds__(128) void na_kernel(const float* __restrict__ rpb)
{
    float* kv = na_sm;
    float* qo = na_sm + 64 * KVW;

    int tid = threadIdx.x;
    int n0 = blockIdx.x * LT;
    int bh = blockIdx.y;
    int h = bh & (H_ - 1);

    const float* kbase = g_k + (size_t)bh * L_ * D_;
    const float* vbase = g_v + (size_t)bh * L_ * D_;
    const float* qbase = g_q + (size_t)bh * L_ * D_;

    for (int idx = tid; idx < 140 * 64; idx += 128) {
        int col = idx >> 6, d = idx & 63;
        int p = n0 - 6 + col;
        p = max(0, min(p, L_ - 1));
        kv[d * KVW + col] = kbase[(size_t)p * 64 + d];
    }
    for (int idx = tid; idx < LT * 64; idx += 128) {
        int l = idx >> 6, d = idx & 63;
        qo[d * QW + l] = qbase[(size_t)(n0 + l) * 64 + d];
    }
    __syncthreads();

    int l = tid;
    int lg = n0 + l;
    int ni = max(0, min(lg - (KNL / 2), L_ - KNL));
    int col0 = ni - (n0 - 6);

    float s[KNL];
    #pragma unroll
    for (int j = 0; j < KNL; j++) s[j] = 0.f;
    for (int d = 0; d < 64; d++) {
        float qd = qo[d * QW + l];
        const float* krow = &kv[d * KVW + col0];
        #pragma unroll
        for (int j = 0; j < KNL; j++) s[j] += qd * krow[j];
    }

    int pb = h * (2 * KNL - 1) + (ni - lg + (KNL - 1));
    float mx = -1e30f;
    #pragma unroll
    for (int j = 0; j < KNL; j++) { s[j] += rpb[pb + j]; mx = fmaxf(mx, s[j]); }
    float sum = 0.f;
    #pragma unroll
    for (int j = 0; j < KNL; j++) { s[j] = __expf(s[j] - mx); sum += s[j]; }
    float inv = 1.f / sum;
    #pragma unroll
    for (int j = 0; j < KNL; j++) s[j] *= inv;

    __syncthreads();
    for (int idx = tid; idx < 140 * 64; idx += 128) {
        int col = idx >> 6, d = idx & 63;
        int p = n0 - 6 + col;
        p = max(0, min(p, L_ - 1));
        kv[d * KVW + col] = vbase[(size_t)p * 64 + d];
    }
    __syncthreads();

    for (int d = 0; d < 64; d++) {
        const float* vrow = &kv[d * KVW + col0];
        float o = 0.f;
        #pragma unroll
        for (int j = 0; j < KNL; j++) o += s[j] * vrow[j];
        qo[d * QW + l] = o;
    }
    __syncthreads();

    int b = bh >> 4;
    size_t obase = ((size_t)b * L_ + n0) * C_ + h * 64;
    for (int idx = tid; idx < LT * 64; idx += 128) {
        int l2 = idx >> 6, d = idx & 63;
        g_att_h[obase + (size_t)l2 * C_ + d] = __float2half_rn(qo[d * QW + l2]);
    }
}

// ---------------- host: tensormap encode (guarded) ----------------
typedef CUresult (*PFN_encodeTiled)(
    CUtensorMap*, CUtensorMapDataType, cuuint32_t, void*,
    const cuuint64_t*, const cuuint64_t*, const cuuint32_t*, const cuuint32_t*,
    CUtensorMapInterleave, CUtensorMapSwizzle, CUtensorMapL2promotion,
    CUtensorMapFloatOOBfill);

static bool make_map(PFN_encodeTiled fn, CUtensorMap* m, void* base,
                     uint64_t rows, uint32_t boxRows) {
    if (!fn) return false;
    cuuint64_t dims[2]    = {(cuuint64_t)K_TOT, (cuuint64_t)rows};
    cuuint64_t strides[1] = {(cuuint64_t)K_TOT * 2};
    cuuint32_t box[2]     = {64, boxRows};
    cuuint32_t es[2]      = {1, 1};
    CUresult r = fn(m, CU_TENSOR_MAP_DATA_TYPE_FLOAT16, 2, base,
                    dims, strides, box, es,
                    CU_TENSOR_MAP_INTERLEAVE_NONE, CU_TENSOR_MAP_SWIZZLE_128B,
                    CU_TENSOR_MAP_L2_PROMOTION_L2_128B,
                    CU_TENSOR_MAP_FLOAT_OOB_FILL_NONE);
    return r == CUDA_SUCCESS;
}

// ---------------- launch ----------------
extern "C" void kernel_launch(void* const* d_in, const int* in_sizes, int n_in,
                              void* d_out, int out_size)
{
    const float* x      = (const float*)d_in[0];
    const float* w_qkv  = (const float*)d_in[1];
    const float* b_qkv  = (const float*)d_in[2];
    const float* rpb    = (const float*)d_in[3];
    const float* w_proj = (const float*)d_in[4];
    const float* b_proj = (const float*)d_in[5];
    float* out = (float*)d_out;

    static bool attr_set = false;
    if (!attr_set) {
        cudaFuncSetAttribute(na_kernel, cudaFuncAttributeMaxDynamicSharedMemorySize, NA_SMEM);
        cudaFuncSetAttribute(tma_gemm_kernel, cudaFuncAttributeMaxDynamicSharedMemorySize, GEMM_SMEM_TMA);
        cudaFuncSetAttribute(cpa_gemm_kernel, cudaFuncAttributeMaxDynamicSharedMemorySize, GEMM_SMEM_CPA);
        attr_set = true;
    }

    __half *xh, *ath, *wq, *wp;
    cudaGetSymbolAddress((void**)&xh,  g_x_h);
    cudaGetSymbolAddress((void**)&ath, g_att_h);
    cudaGetSymbolAddress((void**)&wq,  g_wqkvT);
    cudaGetSymbolAddress((void**)&wp,  g_wprojT);

    // resolve the encoder once; any failure -> cp.async fallback
    static PFN_encodeTiled enc = nullptr;
    static bool enc_tried = false;
    if (!enc_tried) {
        enc_tried = true;
        void* p = nullptr;
        cudaDriverEntryPointQueryResult qr = cudaDriverEntryPointSuccess;
        cudaError_t e = cudaGetDriverEntryPoint("cuTensorMapEncodeTiled", &p,
                                                cudaEnableDefault, &qr);
        if (e == cudaSuccess && qr == cudaDriverEntryPointSuccess && p)
            enc = (PFN_encodeTiled)p;
        else
            cudaGetLastError();   // clear sticky error
    }

    CUtensorMap mapX, mapAtt, mapWq, mapWp;
    bool use_tma = true;
    use_tma &= make_map(enc, &mapX,   xh,  M_TOT,  128);
    use_tma &= make_map(enc, &mapAtt, ath, M_TOT,  128);
    use_tma &= make_map(enc, &mapWq,  wq,  3 * C_, 256);
    use_tma &= make_map(enc, &mapWp,  wp,  C_,     256);

    // 1. x -> fp16
    size_t n4 = (size_t)M_TOT * K_TOT / 4;
    convert_half_kernel<<<(unsigned)((n4 + 255) / 256), 256>>>(x, xh, n4);

    // 2. transpose weights to fp16 [N][K]
    transpose_half_kernel<<<dim3(3 * C_ / 32, C_ / 32), dim3(32, 32)>>>(
        w_qkv, wq, C_, 3 * C_);
    transpose_half_kernel<<<dim3(C_ / 32, C_ / 32), dim3(32, 32)>>>(
        w_proj, wp, C_, C_);

    dim3 gridQ(3 * C_ / 256, M_TOT / 128);
    dim3 gridP(C_ / 256, M_TOT / 128);

    // 3. QKV GEMM -> scattered q/k/v
    if (use_tma)
        tma_gemm_kernel<<<gridQ, 512, GEMM_SMEM_TMA>>>(mapX, mapWq, b_qkv, out, 3 * C_, 0);
    else
        cpa_gemm_kernel<<<gridQ, 512, GEMM_SMEM_CPA>>>(xh, wq, b_qkv, out, 3 * C_, 0);

    // 4. neighborhood attention -> att fp16
    na_kernel<<<dim3(L_ / LT, B_ * H_), 128, NA_SMEM>>>(rpb);

    // 5. proj GEMM -> out
    if (use_tma)
        tma_gemm_kernel<<<gridP, 512, GEMM_SMEM_TMA>>>(mapAtt, mapWp, b_proj, out, C_, 1);
    else
        cpa_gemm_kernel<<<gridP, 512, GEMM_SMEM_CPA>>>(ath, wp, b_proj, out, C_, 1);
}

// round 10
// speedup vs baseline: 6.1247x; 1.1220x over previous
#include <cuda_runtime.h>
#include <cuda_fp16.h>
#include <cuda.h>
#include <cstdint>

#define B_  4
#define L_  4096
#define H_  16
#define D_  64
#define C_  1024
#define KNL 13
#define M_TOT (B_ * L_)          // 16384
#define K_TOT C_                 // 1024

typedef unsigned long long u64;

// ---------------- device scratch (no allocation allowed) ----------------
__device__ float g_q[(size_t)B_*H_*L_*D_];
__device__ float g_k[(size_t)B_*H_*L_*D_];
__device__ float g_v[(size_t)B_*H_*L_*D_];
__device__ __half g_x_h[(size_t)M_TOT*K_TOT];
__device__ __half g_att_h[(size_t)M_TOT*K_TOT];
__device__ __half g_wqkvT[(size_t)3*C_*C_];
__device__ __half g_wprojT[(size_t)C_*C_];

// ---------------- helpers ----------------
__device__ __forceinline__ uint32_t smem_u32(const void* p) {
    uint32_t a;
    asm("{ .reg .u64 t; cvta.to.shared.u64 t, %1; cvt.u32.u64 %0, t; }"
        : "=r"(a) : "l"(p));
    return a;
}
#define MBARRIER_INIT(addr, cnt) \
    asm volatile("mbarrier.init.shared.b64 [%0], %1;" :: "r"(addr), "r"(cnt) : "memory")
#define MBARRIER_EXPECT_TX(addr, bytes) \
    asm volatile("mbarrier.arrive.expect_tx.shared.b64 _, [%0], %1;" \
                 :: "r"(addr), "r"((uint32_t)(bytes)) : "memory")
#define MBARRIER_ARRIVE(addr) \
    asm volatile("mbarrier.arrive.release.cta.shared.b64 _, [%0];" :: "r"(addr) : "memory")
// bounded wait: never hangs the GPU; a stuck wait becomes a wrong answer.
__device__ __forceinline__ void mbar_wait(uint32_t mbar, uint32_t parity) {
    for (int it = 0; it < 65536; it++) {
        uint32_t done;
        asm volatile("{\n\t.reg .pred p;\n\t"
            "mbarrier.try_wait.parity.acquire.cta.shared::cta.b64 p, [%1], %2, 0x2710;\n\t"
            "selp.b32 %0, 1, 0, p;\n\t}"
            : "=r"(done) : "r"(mbar), "r"(parity) : "memory");
        if (done) return;
    }
}
#define FENCE_PROXY_ASYNC() asm volatile("fence.proxy.async.shared::cta;" ::: "memory")

__device__ __forceinline__ void tma2d(uint32_t dst, const void* map,
                                      int cx, int cy, uint32_t mbar) {
    asm volatile(
        "cp.async.bulk.tensor.2d.shared::cta.global.tile.mbarrier::complete_tx::bytes "
        "[%0], [%1, {%2, %3}], [%4];"
        :: "r"(dst), "l"(map), "r"(cx), "r"(cy), "r"(mbar) : "memory");
}

__device__ __forceinline__ void cpa16(uint32_t dst, const void* src) {
    asm volatile("cp.async.cg.shared.global [%0], [%1], 16;" :: "r"(dst), "l"(src));
}
#define CP_COMMIT() asm volatile("cp.async.commit_group;" ::: "memory")
#define CP_WAIT1()  asm volatile("cp.async.wait_group 1;" ::: "memory")

#define LDSM_X4(r, addr) \
    asm volatile("ldmatrix.sync.aligned.m8n8.x4.shared.b16 {%0,%1,%2,%3}, [%4];" \
        : "=r"((r)[0]), "=r"((r)[1]), "=r"((r)[2]), "=r"((r)[3]) : "r"(addr))

#define MMA_F16(acc, a, b0v, b1v) \
    asm volatile("mma.sync.aligned.m16n8k16.row.col.f32.f16.f16.f32 " \
        "{%0,%1,%2,%3},{%4,%5,%6,%7},{%8,%9},{%0,%1,%2,%3};" \
        : "+f"((acc)[0]), "+f"((acc)[1]), "+f"((acc)[2]), "+f"((acc)[3]) \
        : "r"((a)[0]), "r"((a)[1]), "r"((a)[2]), "r"((a)[3]), "r"(b0v), "r"(b1v))

__device__ __forceinline__ u64 bc2(float x) {
    u64 r; unsigned xi = __float_as_uint(x);
    asm("mov.b64 %0, {%1, %1};" : "=l"(r) : "r"(xi));
    return r;
}
__device__ __forceinline__ void fma2(u64& d, u64 a, u64 b) {
    asm("fma.rn.f32x2 %0, %1, %2, %0;" : "+l"(d) : "l"(a), "l"(b));
}
__device__ __forceinline__ float lo2(u64 v) { return __uint_as_float((unsigned)(v & 0xffffffffull)); }
__device__ __forceinline__ float hi2(u64 v) { return __uint_as_float((unsigned)(v >> 32)); }
__device__ __forceinline__ u64 pk2(float a, float b) {
    u64 r;
    asm("mov.b64 %0, {%1, %2};" : "=l"(r) : "r"(__float_as_uint(a)), "r"(__float_as_uint(b)));
    return r;
}

// ---------------- conversion kernels ----------------
__global__ __launch_bounds__(256) void convert_half_kernel(
    const float* __restrict__ src, __half* __restrict__ dst, size_t n4)
{
    size_t i = (size_t)blockIdx.x * 256 + threadIdx.x;
    if (i >= n4) return;
    float4 v = ((const float4*)src)[i];
    __half2 a = __floats2half2_rn(v.x, v.y);
    __half2 b = __floats2half2_rn(v.z, v.w);
    ((uint2*)dst)[i] = make_uint2(*(uint32_t*)&a, *(uint32_t*)&b);
}

__global__ __launch_bounds__(1024) void transpose_half_kernel(
    const float* __restrict__ w, __half* __restrict__ t, int K, int N)
{
    __shared__ float sm[32][33];
    int n0 = blockIdx.x * 32, k0 = blockIdx.y * 32;
    int tx = threadIdx.x, ty = threadIdx.y;
    sm[ty][tx] = w[(size_t)(k0 + ty) * N + n0 + tx];
    __syncthreads();
    t[(size_t)(n0 + ty) * K + k0 + tx] = __float2half_rn(sm[tx][ty]);
}

// ---------------- shared GEMM config ----------------
// CTA 128(M) x 256(N), 512 threads = 16 warps (2M x 8N), warp tile 64x32.
// Stage: A (128x64 fp16, 16K) @0 | B (256x64 fp16, 32K) @16K ; stride 48K.
#define STG 49152
#define NSTG_TMA 4
#define NSTG_CPA 3
#define GEMM_SMEM_TMA (NSTG_TMA * STG + 1024)
#define GEMM_SMEM_CPA (NSTG_CPA * STG + 1024)
#define NCHUNK (K_TOT / 64)

extern __shared__ char gsm_raw[];

struct FragCtx {
    uint32_t xrA, xrB, aRowOff, bRowOff;
    int kbA, kbB;
};
__device__ __forceinline__ FragCtx frag_ctx(int lane, int warpM, int warpN) {
    FragCtx f;
    int g = lane >> 3, rr = lane & 7;
    int rA = (g & 1) * 8 + rr;
    f.kbA = (g >> 1) * 16;
    f.xrA = (uint32_t)((rA & 7) << 4);
    int rB = (g >> 1) * 8 + rr;
    f.kbB = (g & 1) * 16;
    f.xrB = (uint32_t)(rr << 4);
    f.aRowOff = (uint32_t)(warpM + rA) * 128;
    f.bRowOff = (uint32_t)(warpN + rB) * 128;
    return f;
}

__device__ __forceinline__ void compute_chunk(
    uint32_t sbase, const FragCtx& f, float acc[4][4][4])
{
    #pragma unroll
    for (int ks = 0; ks < 4; ks++) {
        uint32_t kterA = (uint32_t)((f.kbA + ks * 32)) ^ f.xrA;
        uint32_t kterB = (uint32_t)((f.kbB + ks * 32)) ^ f.xrB;
        uint32_t bh[2][4];
        #pragma unroll
        for (int jn = 0; jn < 2; jn++) {
            uint32_t bd = sbase + 16384 + f.bRowOff + (uint32_t)(jn * 2048) + kterB;
            LDSM_X4(bh[jn], bd);
        }
        #pragma unroll
        for (int im = 0; im < 4; im++) {
            uint32_t ah[4];
            uint32_t ad = sbase + f.aRowOff + (uint32_t)(im * 2048) + kterA;
            LDSM_X4(ah, ad);
            #pragma unroll
            for (int in = 0; in < 4; in++) {
                int jn = in >> 1, s = (in & 1) * 2;
                MMA_F16(acc[im][in], ah, bh[jn][s], bh[jn][s + 1]);
            }
        }
    }
}

__device__ __forceinline__ void gemm_epilogue(
    float acc[4][4][4], const float* bias, float* Cout,
    int m0, int n0, int warpM, int warpN, int lane, int Nt, int mode)
{
    int r0 = lane >> 2;
    int cp2 = (lane & 3) * 2;
    #pragma unroll
    for (int in = 0; in < 4; in++) {
        int n = n0 + warpN + in * 8 + cp2;
        float2 bs = *(const float2*)&bias[n];
        if (mode == 0) {
            int which = n >> 10, rem = n & 1023, h = rem >> 6, d = rem & 63;
            float scale = (which == 0) ? 0.125f : 1.0f;
            float* dst = (which == 0) ? g_q : (which == 1) ? g_k : g_v;
            #pragma unroll
            for (int im = 0; im < 4; im++) {
                #pragma unroll
                for (int half = 0; half < 2; half++) {
                    int m = m0 + warpM + im * 16 + r0 + half * 8;
                    int b = m >> 12, l = m & 4095;
                    float2 o;
                    o.x = (acc[im][in][half * 2 + 0] + bs.x) * scale;
                    o.y = (acc[im][in][half * 2 + 1] + bs.y) * scale;
                    *(float2*)&dst[(((size_t)(b * H_ + h)) * L_ + l) * D_ + d] = o;
                }
            }
        } else {
            #pragma unroll
            for (int im = 0; im < 4; im++) {
                #pragma unroll
                for (int half = 0; half < 2; half++) {
                    int m = m0 + warpM + im * 16 + r0 + half * 8;
                    float2 o;
                    o.x = acc[im][in][half * 2 + 0] + bs.x;
                    o.y = acc[im][in][half * 2 + 1] + bs.y;
                    *(float2*)&Cout[(size_t)m * Nt + n] = o;
                }
            }
        }
    }
}

// ---------------- TMA GEMM (full/empty mbarrier ring, no per-chunk CTA sync) --
__global__ __launch_bounds__(512, 1) void tma_gemm_kernel(
    const __grid_constant__ CUtensorMap mapA,
    const __grid_constant__ CUtensorMap mapB,
    const float* __restrict__ bias, float* __restrict__ Cout, int Nt, int mode)
{
    __shared__ __align__(8) unsigned long long s_full[NSTG_TMA];
    __shared__ __align__(8) unsigned long long s_empty[NSTG_TMA];

    int tid = threadIdx.x;
    int lane = tid & 31, wid = tid >> 5;
    int m0 = blockIdx.y * 128, n0 = blockIdx.x * 256;
    int warpM = (wid & 1) * 64, warpN = (wid >> 1) * 32;

    uint32_t dynb = smem_u32(gsm_raw);
    uint32_t SB = (dynb + 1023) & ~1023u;

    if (tid == 0) {
        #pragma unroll
        for (int s = 0; s < NSTG_TMA; s++) {
            MBARRIER_INIT(smem_u32(&s_full[s]), 1);
            MBARRIER_INIT(smem_u32(&s_empty[s]), 16);
        }
        FENCE_PROXY_ASYNC();
    }
    __syncthreads();

    if (tid == 0) {
        #pragma unroll
        for (int p = 0; p < NSTG_TMA - 1; p++) {
            uint32_t mb = smem_u32(&s_full[p]);
            uint32_t dst = SB + (uint32_t)p * STG;
            MBARRIER_EXPECT_TX(mb, STG);
            tma2d(dst,         &mapA, p * 64, m0, mb);
            tma2d(dst + 16384, &mapB, p * 64, n0, mb);
        }
    }

    FragCtx f = frag_ctx(lane, warpM, warpN);

    float acc[4][4][4];
    #pragma unroll
    for (int i = 0; i < 4; i++)
        #pragma unroll
        for (int j = 0; j < 4; j++)
            #pragma unroll
            for (int q = 0; q < 4; q++) acc[i][j][q] = 0.f;

    for (int c = 0; c < NCHUNK; c++) {
        // producer: issue chunk c+3 once its buffer has drained
        if (tid == 0 && c + NSTG_TMA - 1 < NCHUNK) {
            int p = c + NSTG_TMA - 1, b = p & (NSTG_TMA - 1);
            if (p >= NSTG_TMA)
                mbar_wait(smem_u32(&s_empty[b]), ((p >> 2) - 1) & 1);
            uint32_t mb = smem_u32(&s_full[b]);
            uint32_t dst = SB + (uint32_t)b * STG;
            MBARRIER_EXPECT_TX(mb, STG);
            tma2d(dst,         &mapA, p * 64, m0, mb);
            tma2d(dst + 16384, &mapB, p * 64, n0, mb);
        }
        int buf = c & (NSTG_TMA - 1);
        mbar_wait(smem_u32(&s_full[buf]), (c >> 2) & 1);
        compute_chunk(SB + (uint32_t)buf * STG, f, acc);
        if (lane == 0) MBARRIER_ARRIVE(smem_u32(&s_empty[buf]));
    }

    gemm_epilogue(acc, bias, Cout, m0, n0, warpM, warpN, lane, Nt, mode);
}

// ---------------- cp.async fallback GEMM (unchanged structure) ----------------
__device__ __forceinline__ void ld_stage_cpa(
    uint32_t sb, const __half* Ah, const __half* Bh,
    int m0, int n0, int kc, int tid)
{
    {
        int e = tid;
        int row = e >> 2, c16 = (e & 3) * 2;
        uint32_t off = row * 128 + c16 * 16;
        uint32_t sw0 = off ^ (uint32_t)((row & 7) << 4);
        uint32_t sw1 = (off + 16) ^ (uint32_t)((row & 7) << 4);
        size_t ga = (size_t)(m0 + row) * K_TOT + kc + c16 * 8;
        cpa16(sb + sw0, Ah + ga);
        cpa16(sb + sw1, Ah + ga + 8);
    }
    #pragma unroll
    for (int i = 0; i < 4; i++) {
        int e = tid + i * 512;
        int row = e >> 3, c16 = e & 7;
        uint32_t off = row * 128 + c16 * 16;
        uint32_t sw = off ^ (uint32_t)((row & 7) << 4);
        size_t gb = (size_t)(n0 + row) * K_TOT + kc + c16 * 8;
        cpa16(sb + 16384 + sw, Bh + gb);
    }
}

__global__ __launch_bounds__(512, 1) void cpa_gemm_kernel(
    const __half* __restrict__ Ah, const __half* __restrict__ Bh,
    const float* __restrict__ bias, float* __restrict__ Cout, int Nt, int mode)
{
    int tid = threadIdx.x;
    int lane = tid & 31, wid = tid >> 5;
    int m0 = blockIdx.y * 128, n0 = blockIdx.x * 256;
    int warpM = (wid & 1) * 64, warpN = (wid >> 1) * 32;

    uint32_t dynb = smem_u32(gsm_raw);
    uint32_t SB = (dynb + 1023) & ~1023u;

    FragCtx f = frag_ctx(lane, warpM, warpN);

    float acc[4][4][4];
    #pragma unroll
    for (int i = 0; i < 4; i++)
        #pragma unroll
        for (int j = 0; j < 4; j++)
            #pragma unroll
            for (int q = 0; q < 4; q++) acc[i][j][q] = 0.f;

    ld_stage_cpa(SB,       Ah, Bh, m0, n0, 0,  tid);
    CP_COMMIT();
    ld_stage_cpa(SB + STG, Ah, Bh, m0, n0, 64, tid);
    CP_COMMIT();

    int buf = 0;
    for (int c = 0; c < NCHUNK; c++) {
        CP_WAIT1();
        __syncthreads();
        if (c + 2 < NCHUNK) {
            int nb = buf + 2; if (nb >= NSTG_CPA) nb -= NSTG_CPA;
            ld_stage_cpa(SB + (uint32_t)nb * STG, Ah, Bh, m0, n0, (c + 2) * 64, tid);
        }
        CP_COMMIT();
        compute_chunk(SB + (uint32_t)buf * STG, f, acc);
        buf++; if (buf >= NSTG_CPA) buf = 0;
    }

    gemm_epilogue(acc, bias, Cout, m0, n0, warpM, warpN, lane, Nt, mode);
}

// ---------------- neighborhood attention (f32x2 aligned-window) ----------------
#define LT  128
#define KVW 148            // multiple of 4 -> 16B-aligned float4 rows
#define NA_COLS 144        // filled columns (max read col = 142)
#define QW  129
#define NA_SMEM ((64 * KVW + 64 * QW) * 4)

extern __shared__ float na_sm[];

__global__ __launch_bounds__(128) void na_kernel(const float* __restrict__ rpb)
{
    float* kv = na_sm;                 // 64 x 148
    float* qo = na_sm + 64 * KVW;      // 64 x 129

    int tid = threadIdx.x;
    int n0 = blockIdx.x * LT;
    int bh = blockIdx.y;
    int h = bh & (H_ - 1);

    const float* kbase = g_k + (size_t)bh * L_ * D_;
    const float* vbase = g_v + (size_t)bh * L_ * D_;
    const float* qbase = g_q + (size_t)bh * L_ * D_;

    for (int idx = tid; idx < NA_COLS * 64; idx += 128) {
        int col = idx >> 6, d = idx & 63;
        int p = n0 - 6 + col;
        p = max(0, min(p, L_ - 1));
        kv[d * KVW + col] = kbase[(size_t)p * 64 + d];
    }
    for (int idx = tid; idx < LT * 64; idx += 128) {
        int l = idx >> 6, d = idx & 63;
        qo[d * QW + l] = qbase[(size_t)(n0 + l) * 64 + d];
    }
    __syncthreads();

    int l = tid;
    int lg = n0 + l;
    int ni = max(0, min(lg - (KNL / 2), L_ - KNL));
    int col0 = ni - (n0 - 6);          // 0..133
    int wstart = col0 & ~3;            // aligned window base
    int shift = col0 - wstart;         // 0..3

    // 16 packed score accumulators (8 x f32x2) over aligned window
    u64 sw2[8];
    #pragma unroll
    for (int i = 0; i < 8; i++) sw2[i] = 0ull;

    for (int d = 0; d < 64; d++) {
        float qd = qo[d * QW + l];
        u64 q2 = bc2(qd);
        const ulonglong2* kr = (const ulonglong2*)&kv[d * KVW + wstart];
        ulonglong2 k01 = kr[0], k23 = kr[1], k45 = kr[2], k67 = kr[3];
        fma2(sw2[0], q2, k01.x); fma2(sw2[1], q2, k01.y);
        fma2(sw2[2], q2, k23.x); fma2(sw2[3], q2, k23.y);
        fma2(sw2[4], q2, k45.x); fma2(sw2[5], q2, k45.y);
        fma2(sw2[6], q2, k67.x); fma2(sw2[7], q2, k67.y);
    }

    float sw[16];
    #pragma unroll
    for (int i = 0; i < 8; i++) { sw[2 * i] = lo2(sw2[i]); sw[2 * i + 1] = hi2(sw2[i]); }

    int pb = h * (2 * KNL - 1) + (ni - lg + (KNL - 1));
    float mx = -1e30f;
    #pragma unroll
    for (int w = 0; w < 16; w++) {
        int bi = w - shift;
        bool inb = (bi >= 0) && (bi < KNL);
        sw[w] = inb ? (sw[w] + rpb[pb + (inb ? bi : 0)]) : -1e30f;
        mx = fmaxf(mx, sw[w]);
    }
    float sum = 0.f;
    #pragma unroll
    for (int w = 0; w < 16; w++) { sw[w] = __expf(sw[w] - mx); sum += sw[w]; }
    float inv = 1.f / sum;
    u64 p2[8];
    #pragma unroll
    for (int i = 0; i < 8; i++) p2[i] = pk2(sw[2 * i] * inv, sw[2 * i + 1] * inv);

    __syncthreads();
    for (int idx = tid; idx < NA_COLS * 64; idx += 128) {
        int col = idx >> 6, d = idx & 63;
        int p = n0 - 6 + col;
        p = max(0, min(p, L_ - 1));
        kv[d * KVW + col] = vbase[(size_t)p * 64 + d];
    }
    __syncthreads();

    for (int d = 0; d < 64; d++) {
        const ulonglong2* vr = (const ulonglong2*)&kv[d * KVW + wstart];
        ulonglong2 v01 = vr[0], v23 = vr[1], v45 = vr[2], v67 = vr[3];
        u64 o2 = 0ull;
        fma2(o2, p2[0], v01.x); fma2(o2, p2[1], v01.y);
        fma2(o2, p2[2], v23.x); fma2(o2, p2[3], v23.y);
        fma2(o2, p2[4], v45.x); fma2(o2, p2[5], v45.y);
        fma2(o2, p2[6], v67.x); fma2(o2, p2[7], v67.y);
        qo[d * QW + l] = lo2(o2) + hi2(o2);
    }
    __syncthreads();

    int b = bh >> 4;
    size_t obase = ((size_t)b * L_ + n0) * C_ + h * 64;
    for (int idx = tid; idx < LT * 64; idx += 128) {
        int l2 = idx >> 6, d = idx & 63;
        g_att_h[obase + (size_t)l2 * C_ + d] = __float2half_rn(qo[d * QW + l2]);
    }
}

// ---------------- host: tensormap encode (guarded) ----------------
typedef CUresult (*PFN_encodeTiled)(
    CUtensorMap*, CUtensorMapDataType, cuuint32_t, void*,
    const cuuint64_t*, const cuuint64_t*, const cuuint32_t*, const cuuint32_t*,
    CUtensorMapInterleave, CUtensorMapSwizzle, CUtensorMapL2promotion,
    CUtensorMapFloatOOBfill);

static bool make_map(PFN_encodeTiled fn, CUtensorMap* m, void* base,
                     uint64_t rows, uint32_t boxRows) {
    if (!fn) return false;
    cuuint64_t dims[2]    = {(cuuint64_t)K_TOT, (cuuint64_t)rows};
    cuuint64_t strides[1] = {(cuuint64_t)K_TOT * 2};
    cuuint32_t box[2]     = {64, boxRows};
    cuuint32_t es[2]      = {1, 1};
    CUresult r = fn(m, CU_TENSOR_MAP_DATA_TYPE_FLOAT16, 2, base,
                    dims, strides, box, es,
                    CU_TENSOR_MAP_INTERLEAVE_NONE, CU_TENSOR_MAP_SWIZZLE_128B,
                    CU_TENSOR_MAP_L2_PROMOTION_L2_128B,
                    CU_TENSOR_MAP_FLOAT_OOB_FILL_NONE);
    return r == CUDA_SUCCESS;
}

// ---------------- launch ----------------
extern "C" void kernel_launch(void* const* d_in, const int* in_sizes, int n_in,
                              void* d_out, int out_size)
{
    const float* x      = (const float*)d_in[0];
    const float* w_qkv  = (const float*)d_in[1];
    const float* b_qkv  = (const float*)d_in[2];
    const float* rpb    = (const float*)d_in[3];
    const float* w_proj = (const float*)d_in[4];
    const float* b_proj = (const float*)d_in[5];
    float* out = (float*)d_out;

    static bool attr_set = false;
    if (!attr_set) {
        cudaFuncSetAttribute(na_kernel, cudaFuncAttributeMaxDynamicSharedMemorySize, NA_SMEM);
        cudaFuncSetAttribute(tma_gemm_kernel, cudaFuncAttributeMaxDynamicSharedMemorySize, GEMM_SMEM_TMA);
        cudaFuncSetAttribute(cpa_gemm_kernel, cudaFuncAttributeMaxDynamicSharedMemorySize, GEMM_SMEM_CPA);
        attr_set = true;
    }

    __half *xh, *ath, *wq, *wp;
    cudaGetSymbolAddress((void**)&xh,  g_x_h);
    cudaGetSymbolAddress((void**)&ath, g_att_h);
    cudaGetSymbolAddress((void**)&wq,  g_wqkvT);
    cudaGetSymbolAddress((void**)&wp,  g_wprojT);

    static PFN_encodeTiled enc = nullptr;
    static bool enc_tried = false;
    if (!enc_tried) {
        enc_tried = true;
        void* p = nullptr;
        cudaDriverEntryPointQueryResult qr = cudaDriverEntryPointSuccess;
        cudaError_t e = cudaGetDriverEntryPoint("cuTensorMapEncodeTiled", &p,
                                                cudaEnableDefault, &qr);
        if (e == cudaSuccess && qr == cudaDriverEntryPointSuccess && p)
            enc = (PFN_encodeTiled)p;
        else
            cudaGetLastError();
    }

    CUtensorMap mapX, mapAtt, mapWq, mapWp;
    bool use_tma = true;
    use_tma &= make_map(enc, &mapX,   xh,  M_TOT,  128);
    use_tma &= make_map(enc, &mapAtt, ath, M_TOT,  128);
    use_tma &= make_map(enc, &mapWq,  wq,  3 * C_, 256);
    use_tma &= make_map(enc, &mapWp,  wp,  C_,     256);

    size_t n4 = (size_t)M_TOT * K_TOT / 4;
    convert_half_kernel<<<(unsigned)((n4 + 255) / 256), 256>>>(x, xh, n4);

    transpose_half_kernel<<<dim3(3 * C_ / 32, C_ / 32), dim3(32, 32)>>>(
        w_qkv, wq, C_, 3 * C_);
    transpose_half_kernel<<<dim3(C_ / 32, C_ / 32), dim3(32, 32)>>>(
        w_proj, wp, C_, C_);

    dim3 gridQ(3 * C_ / 256, M_TOT / 128);
    dim3 gridP(C_ / 256, M_TOT / 128);

    if (use_tma)
        tma_gemm_kernel<<<gridQ, 512, GEMM_SMEM_TMA>>>(mapX, mapWq, b_qkv, out, 3 * C_, 0);
    else
        cpa_gemm_kernel<<<gridQ, 512, GEMM_SMEM_CPA>>>(xh, wq, b_qkv, out, 3 * C_, 0);

    na_kernel<<<dim3(L_ / LT, B_ * H_), 128, NA_SMEM>>>(rpb);

    if (use_tma)
        tma_gemm_kernel<<<gridP, 512, GEMM_SMEM_TMA>>>(mapAtt, mapWp, b_proj, out, C_, 1);
    else
        cpa_gemm_kernel<<<gridP, 512, GEMM_SMEM_CPA>>>(ath, wp, b_proj, out, C_, 1);
}